// round 5
// baseline (speedup 1.0000x reference)
#include <cuda_runtime.h>
#include <math.h>
#include <stdint.h>

#define Bn   16
#define Ss   512
#define Dd   512
#define Hh   8
#define HSs  2
#define DKk  64
#define DFFf 2048
#define NGATE 6   // H - HS

// ---------------- scratch (device globals; no allocation allowed) ----------------
__device__ float g_y[Bn*Ss*Dd];
__device__ float g_x[Bn*Ss*Dd];
__device__ float g_qlin[Bn*Ss*Dd];
__device__ float g_v[Bn*Ss*Dd];
__device__ float g_ctx[Bn*Ss*Dd];
__device__ float g_tmp[Bn*Ss*Dd];
__device__ float g_ffn[Bn*Ss*DFFf];
__device__ float g_rmask[Bn*Hh];

// ---------------- TF32 helpers ----------------
__device__ __forceinline__ float to_tf32(float x) {
    uint32_t u;
    asm("cvt.rna.tf32.f32 %0, %1;" : "=r"(u) : "f"(x));
    return __uint_as_float(u);
}

__device__ __forceinline__ void mma_tf32(float c[4], uint32_t a0, uint32_t a1,
                                         uint32_t a2, uint32_t a3,
                                         uint32_t b0, uint32_t b1) {
    asm volatile(
        "mma.sync.aligned.m16n8k8.row.col.f32.tf32.tf32.f32 "
        "{%0,%1,%2,%3}, {%4,%5,%6,%7}, {%8,%9}, {%0,%1,%2,%3};"
        : "+f"(c[0]), "+f"(c[1]), "+f"(c[2]), "+f"(c[3])
        : "r"(a0), "r"(a1), "r"(a2), "r"(a3), "r"(b0), "r"(b1));
}

// ---------------- TF32 tensor-core dense GEMM, 2-stage pipelined ----------------
// C = relu?( A[M,K] @ W[K,N] + bias ), row-major, lda=K, ldb=N, ldc=N.
// BM=128 x BN x BK=32, 256 threads (8 warps, 2M x 4N), warp tile 64 x (BN/4).
// One __syncthreads per k-iter: STS(next) | LDG(next+1) | MMA(cur) | sync.
template<int BN>
__global__ void __launch_bounds__(256) mma_gemm_kernel(
    const float* __restrict__ A, const float* __restrict__ Bm,
    const float* __restrict__ bias, float* __restrict__ C,
    int K, int N, int relu)
{
    constexpr int BM = 128, BK = 32;
    constexpr int WN = BN / 4;
    constexpr int NT = WN / 8;
    constexpr int LDA_S = BK + 4;     // 36
    constexpr int LDB_S = BN + 8;     // 136 / 72
    constexpr int A_F4 = (BM * BK) / (256 * 4);   // 4
    constexpr int B_F4 = (BK * BN) / (256 * 4);   // 4 / 2
    constexpr int SA = BM * LDA_S;
    constexpr int SB = BK * LDB_S;

    extern __shared__ __align__(16) float smg[];
    float* AsS[2] = { smg,      smg + (SA + SB) };
    float* BsS[2] = { smg + SA, smg + (SA + SB) + SA };

    const int tid = threadIdx.x;
    const int warpId = tid >> 5;
    const int lane = tid & 31;
    const int grp = lane >> 2;
    const int tig = lane & 3;
    const int warpM = warpId & 1;
    const int warpN = warpId >> 1;
    const int row0 = blockIdx.y * BM;
    const int col0 = blockIdx.x * BN;

    float4 aReg[A_F4];
    float4 bReg[B_F4];

    auto loadA = [&](int k0) {
        #pragma unroll
        for (int i = 0; i < A_F4; i++) {
            int f4 = tid + i * 256;
            int r = f4 >> 3, kc = (f4 & 7) * 4;
            aReg[i] = *(const float4*)&A[(long long)(row0 + r) * K + k0 + kc];
        }
    };
    auto loadB = [&](int k0) {
        #pragma unroll
        for (int i = 0; i < B_F4; i++) {
            int f4 = tid + i * 256;
            int kr = f4 / (BN / 4), nc = (f4 % (BN / 4)) * 4;
            bReg[i] = *(const float4*)&Bm[(long long)(k0 + kr) * N + col0 + nc];
        }
    };
    auto storeA = [&](int st) {
        float* As = AsS[st];
        #pragma unroll
        for (int i = 0; i < A_F4; i++) {
            int f4 = tid + i * 256;
            int r = f4 >> 3, kc = (f4 & 7) * 4;
            float4 v = aReg[i];
            v.x = to_tf32(v.x); v.y = to_tf32(v.y);
            v.z = to_tf32(v.z); v.w = to_tf32(v.w);
            *(float4*)&As[r * LDA_S + kc] = v;
        }
    };
    auto storeB = [&](int st) {
        float* Bs = BsS[st];
        #pragma unroll
        for (int i = 0; i < B_F4; i++) {
            int f4 = tid + i * 256;
            int kr = f4 / (BN / 4), nc = (f4 % (BN / 4)) * 4;
            float4 v = bReg[i];
            v.x = to_tf32(v.x); v.y = to_tf32(v.y);
            v.z = to_tf32(v.z); v.w = to_tf32(v.w);
            *(float4*)&Bs[kr * LDB_S + nc] = v;
        }
    };

    float acc[4][NT][4];
    #pragma unroll
    for (int mt = 0; mt < 4; mt++)
        #pragma unroll
        for (int nt = 0; nt < NT; nt++)
            #pragma unroll
            for (int q = 0; q < 4; q++) acc[mt][nt][q] = 0.f;

    const int KT = K / BK;

    // prologue: stage0 filled; regs hold k-tile 1
    loadA(0); loadB(0);
    storeA(0); storeB(0);
    if (KT > 1) { loadA(BK); loadB(BK); }
    __syncthreads();

    for (int kt = 0; kt < KT; kt++) {
        const int cur = kt & 1;
        if (kt + 1 < KT) { storeA(cur ^ 1); storeB(cur ^ 1); }
        if (kt + 2 < KT) { loadA((kt + 2) * BK); loadB((kt + 2) * BK); }

        const uint32_t* Asu = reinterpret_cast<const uint32_t*>(AsS[cur]);
        const uint32_t* Bsu = reinterpret_cast<const uint32_t*>(BsS[cur]);

        #pragma unroll
        for (int kk = 0; kk < BK; kk += 8) {
            uint32_t af[4][4];
            #pragma unroll
            for (int mt = 0; mt < 4; mt++) {
                int base = (warpM * 64 + mt * 16 + grp) * LDA_S + kk + tig;
                af[mt][0] = Asu[base];
                af[mt][1] = Asu[base + 8 * LDA_S];
                af[mt][2] = Asu[base + 4];
                af[mt][3] = Asu[base + 8 * LDA_S + 4];
            }
            uint32_t bf[NT][2];
            #pragma unroll
            for (int nt = 0; nt < NT; nt++) {
                int base = (kk + tig) * LDB_S + warpN * WN + nt * 8 + grp;
                bf[nt][0] = Bsu[base];
                bf[nt][1] = Bsu[base + 4 * LDB_S];
            }
            #pragma unroll
            for (int mt = 0; mt < 4; mt++)
                #pragma unroll
                for (int nt = 0; nt < NT; nt++)
                    mma_tf32(acc[mt][nt], af[mt][0], af[mt][1], af[mt][2], af[mt][3],
                             bf[nt][0], bf[nt][1]);
        }
        __syncthreads();
    }

    #pragma unroll
    for (int mt = 0; mt < 4; mt++) {
        #pragma unroll
        for (int nt = 0; nt < NT; nt++) {
            int r0 = row0 + warpM * 64 + mt * 16 + grp;
            int cc = col0 + warpN * WN + nt * 8 + tig * 2;
            float b0 = bias[cc], b1 = bias[cc + 1];
            float v0 = acc[mt][nt][0] + b0;
            float v1 = acc[mt][nt][1] + b1;
            float v2 = acc[mt][nt][2] + b0;
            float v3 = acc[mt][nt][3] + b1;
            if (relu) {
                v0 = fmaxf(v0, 0.f); v1 = fmaxf(v1, 0.f);
                v2 = fmaxf(v2, 0.f); v3 = fmaxf(v3, 0.f);
            }
            *(float2*)&C[(long long)r0 * N + cc]       = make_float2(v0, v1);
            *(float2*)&C[(long long)(r0 + 8) * N + cc] = make_float2(v2, v3);
        }
    }
}

#define SMEM_G128 ((128*36 + 32*136) * 2 * 4)
#define SMEM_G64  ((128*36 + 32*72)  * 2 * 4)

// ---------------- fused flash attention (mma.sync TF32) ----------------
#define FL_QS   0
#define FL_KP   (64*68)
#define FL_VS   (FL_KP + 64*68)
#define FL_REDM (FL_VS + 64*72)
#define FL_REDS (FL_REDM + 128)
#define FL_M    (FL_REDS + 128)
#define FL_L    (FL_M + 64)
#define FL_TOT  (FL_L + 64)
#define FL_BYTES (FL_TOT * 4)

__global__ void __launch_bounds__(256) flash_attn_kernel(
    const float* __restrict__ qlin, const float* __restrict__ v,
    const float* __restrict__ rmask, float* __restrict__ ctx, int mask_flag)
{
    extern __shared__ float sm[];
    float* Qs  = sm + FL_QS;
    float* KPs = sm + FL_KP;
    float* Vs  = sm + FL_VS;
    float* redm = sm + FL_REDM;
    float* reds = sm + FL_REDS;
    float* m_s  = sm + FL_M;
    float* l_s  = sm + FL_L;

    const int z = blockIdx.y;           // b*H + h
    const int b = z >> 3, h = z & 7;
    const int q0 = blockIdx.x * 64;
    const float* Qg = qlin + (long long)b * Ss * Dd + h * 64;
    const float* Vg = v    + (long long)b * Ss * Dd + h * 64;

    const int tid = threadIdx.x;
    const int warpId = tid >> 5, lane = tid & 31;
    const int grp = lane >> 2, tig = lane & 3;
    const int warpM = warpId >> 1, warpN = warpId & 1;
    const int row_a = warpM * 16 + grp;

    #pragma unroll
    for (int i = 0; i < 4; i++) {
        int id = tid + i * 256;
        int r = id >> 4, c4 = (id & 15) * 4;
        float4 q4 = *(const float4*)&Qg[(long long)(q0 + r) * Dd + c4];
        q4.x = to_tf32(q4.x * 0.125f); q4.y = to_tf32(q4.y * 0.125f);
        q4.z = to_tf32(q4.z * 0.125f); q4.w = to_tf32(q4.w * 0.125f);
        *(float4*)&Qs[r * 68 + c4] = q4;
    }
    if (tid < 64) { m_s[tid] = -1e30f; l_s[tid] = 0.f; }

    float Oa[4][4];
    #pragma unroll
    for (int nt = 0; nt < 4; nt++)
        #pragma unroll
        for (int q = 0; q < 4; q++) Oa[nt][q] = 0.f;

    const uint32_t* Qu  = reinterpret_cast<const uint32_t*>(Qs);
    const uint32_t* KPu = reinterpret_cast<const uint32_t*>(KPs);
    const uint32_t* Vu  = reinterpret_cast<const uint32_t*>(Vs);

    const int nTiles = blockIdx.x + 1;

    for (int kt = 0; kt < nTiles; kt++) {
        const int k0 = kt * 64;
        #pragma unroll
        for (int i = 0; i < 4; i++) {
            int id = tid + i * 256;
            int r = id >> 4, c4 = (id & 15) * 4;
            float4 k4 = *(const float4*)&Qg[(long long)(k0 + r) * Dd + c4];
            k4.x = to_tf32(k4.x); k4.y = to_tf32(k4.y);
            k4.z = to_tf32(k4.z); k4.w = to_tf32(k4.w);
            *(float4*)&KPs[r * 68 + c4] = k4;
            float4 v4 = *(const float4*)&Vg[(long long)(k0 + r) * Dd + c4];
            v4.x = to_tf32(v4.x); v4.y = to_tf32(v4.y);
            v4.z = to_tf32(v4.z); v4.w = to_tf32(v4.w);
            *(float4*)&Vs[r * 72 + c4] = v4;
        }
        __syncthreads();

        float scf[4][4];
        #pragma unroll
        for (int nt = 0; nt < 4; nt++)
            #pragma unroll
            for (int q = 0; q < 4; q++) scf[nt][q] = 0.f;

        #pragma unroll
        for (int kk = 0; kk < 64; kk += 8) {
            uint32_t a0 = Qu[(row_a)     * 68 + kk + tig];
            uint32_t a1 = Qu[(row_a + 8) * 68 + kk + tig];
            uint32_t a2 = Qu[(row_a)     * 68 + kk + tig + 4];
            uint32_t a3 = Qu[(row_a + 8) * 68 + kk + tig + 4];
            #pragma unroll
            for (int nt = 0; nt < 4; nt++) {
                int nc = warpN * 32 + nt * 8 + grp;
                uint32_t b0 = KPu[nc * 68 + kk + tig];
                uint32_t b1 = KPu[nc * 68 + kk + tig + 4];
                mma_tf32(scf[nt], a0, a1, a2, a3, b0, b1);
            }
        }

        if (kt == nTiles - 1) {
            int iA = q0 + row_a, iB = iA + 8;
            int limA = iA + (mask_flag ? 1 : 0);
            int limB = iB + (mask_flag ? 1 : 0);
            #pragma unroll
            for (int nt = 0; nt < 4; nt++) {
                int j0 = k0 + warpN * 32 + nt * 8 + tig * 2;
                if (j0     >= limA) scf[nt][0] = -1e30f;
                if (j0 + 1 >= limA) scf[nt][1] = -1e30f;
                if (j0     >= limB) scf[nt][2] = -1e30f;
                if (j0 + 1 >= limB) scf[nt][3] = -1e30f;
            }
        }

        float mA_old = m_s[row_a], mB_old = m_s[row_a + 8];

        float tmA = -1e30f, tmB = -1e30f;
        #pragma unroll
        for (int nt = 0; nt < 4; nt++) {
            tmA = fmaxf(tmA, fmaxf(scf[nt][0], scf[nt][1]));
            tmB = fmaxf(tmB, fmaxf(scf[nt][2], scf[nt][3]));
        }
        tmA = fmaxf(tmA, __shfl_xor_sync(0xffffffffu, tmA, 1));
        tmA = fmaxf(tmA, __shfl_xor_sync(0xffffffffu, tmA, 2));
        tmB = fmaxf(tmB, __shfl_xor_sync(0xffffffffu, tmB, 1));
        tmB = fmaxf(tmB, __shfl_xor_sync(0xffffffffu, tmB, 2));
        if (tig == 0) {
            redm[warpN * 64 + row_a]     = tmA;
            redm[warpN * 64 + row_a + 8] = tmB;
        }
        __syncthreads();

        float mA = fmaxf(mA_old, fmaxf(redm[row_a],     redm[64 + row_a]));
        float mB = fmaxf(mB_old, fmaxf(redm[row_a + 8], redm[64 + row_a + 8]));
        float alA = __expf(mA_old - mA);
        float alB = __expf(mB_old - mB);

        float psA = 0.f, psB = 0.f;
        #pragma unroll
        for (int nt = 0; nt < 4; nt++) {
            float p0 = __expf(scf[nt][0] - mA);
            float p1 = __expf(scf[nt][1] - mA);
            float p2 = __expf(scf[nt][2] - mB);
            float p3 = __expf(scf[nt][3] - mB);
            psA += p0 + p1; psB += p2 + p3;
            int nc = warpN * 32 + nt * 8 + tig * 2;
            KPs[row_a * 68 + nc]           = to_tf32(p0);
            KPs[row_a * 68 + nc + 1]       = to_tf32(p1);
            KPs[(row_a + 8) * 68 + nc]     = to_tf32(p2);
            KPs[(row_a + 8) * 68 + nc + 1] = to_tf32(p3);
            Oa[nt][0] *= alA; Oa[nt][1] *= alA;
            Oa[nt][2] *= alB; Oa[nt][3] *= alB;
        }
        psA += __shfl_xor_sync(0xffffffffu, psA, 1);
        psA += __shfl_xor_sync(0xffffffffu, psA, 2);
        psB += __shfl_xor_sync(0xffffffffu, psB, 1);
        psB += __shfl_xor_sync(0xffffffffu, psB, 2);
        if (tig == 0) {
            reds[warpN * 64 + row_a]     = psA;
            reds[warpN * 64 + row_a + 8] = psB;
        }
        if (warpN == 0 && tig == 0) {
            m_s[row_a]     = mA;
            m_s[row_a + 8] = mB;
        }
        __syncthreads();

        if (warpN == 0 && tig == 0) {
            l_s[row_a]     = alA * l_s[row_a]     + reds[row_a]     + reds[64 + row_a];
            l_s[row_a + 8] = alB * l_s[row_a + 8] + reds[row_a + 8] + reds[64 + row_a + 8];
        }

        #pragma unroll
        for (int kk = 0; kk < 64; kk += 8) {
            uint32_t a0 = KPu[(row_a)     * 68 + kk + tig];
            uint32_t a1 = KPu[(row_a + 8) * 68 + kk + tig];
            uint32_t a2 = KPu[(row_a)     * 68 + kk + tig + 4];
            uint32_t a3 = KPu[(row_a + 8) * 68 + kk + tig + 4];
            #pragma unroll
            for (int nt = 0; nt < 4; nt++) {
                int nc = warpN * 32 + nt * 8 + grp;
                uint32_t b0 = Vu[(kk + tig)     * 72 + nc];
                uint32_t b1 = Vu[(kk + tig + 4) * 72 + nc];
                mma_tf32(Oa[nt], a0, a1, a2, a3, b0, b1);
            }
        }
        __syncthreads();
    }

    float rm = rmask[z];
    float invA = rm / l_s[row_a];
    float invB = rm / l_s[row_a + 8];
    #pragma unroll
    for (int nt = 0; nt < 4; nt++) {
        int col = h * 64 + warpN * 32 + nt * 8 + tig * 2;
        long long oA = ((long long)b * Ss + q0 + row_a) * Dd + col;
        long long oB = oA + 8LL * Dd;
        *(float2*)&ctx[oA] = make_float2(Oa[nt][0] * invA, Oa[nt][1] * invA);
        *(float2*)&ctx[oB] = make_float2(Oa[nt][2] * invB, Oa[nt][3] * invB);
    }
}

// ---------------- pad row 0 ----------------
__global__ void pad_row_kernel(const float* __restrict__ v, const float* __restrict__ rmask,
                               float* __restrict__ ctx)
{
    int z = blockIdx.x;                 // B*H
    int b = z >> 3, h = z & 7;
    int tid = threadIdx.x;              // 256: (chunk 0..3) x (d 0..63)
    int d = tid & 63, chunk = tid >> 6;
    const float* Vg = v + (long long)b * Ss * Dd + h * 64 + d;
    float s = 0.f;
    for (int j = chunk * 128; j < (chunk + 1) * 128; j++)
        s += Vg[(long long)j * Dd];
    __shared__ float red[256];
    red[tid] = s;
    __syncthreads();
    if (tid < 64) {
        float t = red[tid] + red[tid + 64] + red[tid + 128] + red[tid + 192];
        ctx[(long long)b * Ss * Dd + h * 64 + tid] = t * (1.0f / Ss) * rmask[z];
    }
}

// ---------------- residual + LayerNorm ----------------
__global__ void add_ln_kernel(const float* __restrict__ resid, const float* __restrict__ delta,
                              const float* __restrict__ g, const float* __restrict__ b,
                              float* __restrict__ out)
{
    long long base = (long long)blockIdx.x * Dd;
    int tid = threadIdx.x;
    float v0 = resid[base + tid]       + delta[base + tid];
    float v1 = resid[base + tid + 256] + delta[base + tid + 256];
    float s  = v0 + v1;
    float sq = v0 * v0 + v1 * v1;

    __shared__ float rs[8], rq[8];
    #pragma unroll
    for (int o = 16; o; o >>= 1) {
        s  += __shfl_xor_sync(0xffffffffu, s,  o);
        sq += __shfl_xor_sync(0xffffffffu, sq, o);
    }
    if ((tid & 31) == 0) { rs[tid >> 5] = s; rq[tid >> 5] = sq; }
    __syncthreads();
    s = 0.f; sq = 0.f;
    #pragma unroll
    for (int w2 = 0; w2 < 8; w2++) { s += rs[w2]; sq += rq[w2]; }

    float mu   = s * (1.0f / Dd);
    float var  = sq * (1.0f / Dd) - mu * mu;
    float rstd = rsqrtf(var + 1e-5f);
    out[base + tid]       = g[tid]       * ((v0 - mu) * rstd) + b[tid];
    out[base + tid + 256] = g[tid + 256] * ((v1 - mu) * rstd) + b[tid + 256];
}

// ---------------- fused routing: rmask directly (dyn never materialized) ----------------
// grid = Bn, block = 256 (8 warps x 64 tokens each)
__global__ void route_kernel(const float* __restrict__ qlin, const float* __restrict__ wg,
                             float* __restrict__ rmask)
{
    const int b = blockIdx.x;
    const int tid = threadIdx.x, wid = tid >> 5, lane = tid & 31;
    const float* qb = qlin + (long long)b * Ss * Dd;

    float wsum[NGATE];
    #pragma unroll
    for (int g = 0; g < NGATE; g++) wsum[g] = 0.f;

    for (int t = wid; t < Ss; t += 8) {
        const float* q = qb + (long long)t * Dd;
        float acc[NGATE];
        #pragma unroll
        for (int g = 0; g < NGATE; g++) acc[g] = 0.f;
        for (int d = lane; d < Dd; d += 32) {
            float qv = q[d];
            const float* w = wg + d * NGATE;
            #pragma unroll
            for (int g = 0; g < NGATE; g++) acc[g] += qv * w[g];
        }
        #pragma unroll
        for (int g = 0; g < NGATE; g++)
            #pragma unroll
            for (int o = 16; o; o >>= 1) acc[g] += __shfl_xor_sync(0xffffffffu, acc[g], o);

        // all lanes hold identical totals: top-2 + softmax (lane-uniform)
        int i1 = 0;
        #pragma unroll
        for (int g = 1; g < NGATE; g++) if (acc[g] > acc[i1]) i1 = g;
        int i2 = (i1 == 0) ? 1 : 0;
        #pragma unroll
        for (int g = 0; g < NGATE; g++)
            if (g != i1 && acc[g] > acc[i2]) i2 = g;
        float mx = acc[i1], sum = 0.f, e[NGATE];
        #pragma unroll
        for (int g = 0; g < NGATE; g++) { e[g] = expf(acc[g] - mx); sum += e[g]; }
        float inv = 1.0f / sum;
        #pragma unroll
        for (int g = 0; g < NGATE; g++)
            if (g == i1 || g == i2) wsum[g] += e[g] * inv;
    }

    __shared__ float red[8][NGATE];
    if (lane == 0)
        #pragma unroll
        for (int g = 0; g < NGATE; g++) red[wid][g] = wsum[g];
    __syncthreads();
    if (tid < NGATE) {
        float s = 0.f;
        #pragma unroll
        for (int w2 = 0; w2 < 8; w2++) s += red[w2][tid];
        rmask[b * Hh + HSs + tid] = s * (1.0f / Ss);
    }
    if (tid >= NGATE && tid < NGATE + HSs)
        rmask[b * Hh + (tid - NGATE)] = 1.f;
}

// ---------------- host orchestration ----------------
struct Wts {
    const float *wq, *bq, *wv, *bv, *wo, *bo, *wg;
    const float *ln1g, *ln1b, *fw1, *fb1, *fw2, *fb2, *ln2g, *ln2b;
};
struct Scr {
    float *qlin, *v, *ctx, *tmp, *ffn, *rmask;
};

static void gemm_n512(const float* A, const float* Bm, const float* bias, float* C,
                      int M, int K, int relu)
{
    dim3 grid(Dd / 64, M / 128);
    mma_gemm_kernel<64><<<grid, 256, SMEM_G64>>>(A, Bm, bias, C, K, Dd, relu);
}

static void gemm_ffn1(const float* A, const float* Bm, const float* bias, float* C, int M)
{
    dim3 grid(DFFf / 128, M / 128);
    mma_gemm_kernel<128><<<grid, 256, SMEM_G128>>>(A, Bm, bias, C, Dd, DFFf, 1);
}

static void run_block(float* xq, float* xv, int layer, bool mask_flag, bool apply_pos,
                      const Wts& w, const Scr& s, float* finalOut)
{
    const int M = Bn * Ss;
    const long long DD = (long long)Dd * Dd;

    gemm_n512(xq, w.wq + layer * DD, w.bq + layer * Dd, s.qlin, M, Dd, 0);
    gemm_n512(xv, w.wv + layer * DD, w.bv + layer * Dd, s.v,    M, Dd, 0);

    route_kernel<<<Bn, 256>>>(s.qlin, w.wg + (long long)layer * Dd * NGATE, s.rmask);

    flash_attn_kernel<<<dim3(Ss / 64, Bn * Hh), 256, FL_BYTES>>>(
        s.qlin, s.v, s.rmask, s.ctx, mask_flag ? 1 : 0);
    pad_row_kernel<<<Bn * Hh, 256>>>(s.v, s.rmask, s.ctx);

    gemm_n512(s.ctx, w.wo + layer * DD, w.bo + layer * Dd, s.tmp, M, Dd, 0);

    add_ln_kernel<<<M, 256>>>(xq, s.tmp, w.ln1g + layer * Dd, w.ln1b + layer * Dd, xq);

    if (apply_pos) {
        gemm_ffn1(xq, w.fw1 + (long long)layer * Dd * DFFf, w.fb1 + layer * DFFf, s.ffn, M);
        gemm_n512(s.ffn, w.fw2 + (long long)layer * DFFf * Dd, w.fb2 + layer * Dd, s.tmp,
                  M, DFFf, 0);
        float* out2 = finalOut ? finalOut : xq;
        add_ln_kernel<<<M, 256>>>(xq, s.tmp, w.ln2g + layer * Dd, w.ln2b + layer * Dd, out2);
    }
}

extern "C" void kernel_launch(void* const* d_in, const int* in_sizes, int n_in,
                              void* d_out, int out_size)
{
    const float* question    = (const float*)d_in[0];
    const float* interaction = (const float*)d_in[1];
    Wts w;
    w.wq   = (const float*)d_in[2];  w.bq   = (const float*)d_in[3];
    w.wv   = (const float*)d_in[4];  w.bv   = (const float*)d_in[5];
    w.wo   = (const float*)d_in[6];  w.bo   = (const float*)d_in[7];
    w.wg   = (const float*)d_in[8];
    w.ln1g = (const float*)d_in[9];  w.ln1b = (const float*)d_in[10];
    w.fw1  = (const float*)d_in[11]; w.fb1  = (const float*)d_in[12];
    w.fw2  = (const float*)d_in[13]; w.fb2  = (const float*)d_in[14];
    w.ln2g = (const float*)d_in[15]; w.ln2b = (const float*)d_in[16];

    cudaFuncSetAttribute(flash_attn_kernel,
                         cudaFuncAttributeMaxDynamicSharedMemorySize, FL_BYTES);
    cudaFuncSetAttribute(mma_gemm_kernel<64>,
                         cudaFuncAttributeMaxDynamicSharedMemorySize, SMEM_G64);
    cudaFuncSetAttribute(mma_gemm_kernel<128>,
                         cudaFuncAttributeMaxDynamicSharedMemorySize, SMEM_G128);

    float *gx, *gy;
    Scr s;
    cudaGetSymbolAddress((void**)&gx,      g_x);
    cudaGetSymbolAddress((void**)&gy,      g_y);
    cudaGetSymbolAddress((void**)&s.qlin,  g_qlin);
    cudaGetSymbolAddress((void**)&s.v,     g_v);
    cudaGetSymbolAddress((void**)&s.ctx,   g_ctx);
    cudaGetSymbolAddress((void**)&s.tmp,   g_tmp);
    cudaGetSymbolAddress((void**)&s.ffn,   g_ffn);
    cudaGetSymbolAddress((void**)&s.rmask, g_rmask);

    size_t bytes = (size_t)Bn * Ss * Dd * sizeof(float);
    cudaMemcpyAsync(gy, interaction, bytes, cudaMemcpyDeviceToDevice);
    cudaMemcpyAsync(gx, question,    bytes, cudaMemcpyDeviceToDevice);

    // knowledge encoder
    run_block(gy, gy, 0, true,  false, w, s, nullptr);
    run_block(gy, gy, 1, true,  false, w, s, nullptr);
    // question encoder
    run_block(gx, gx, 2, true,  false, w, s, nullptr);
    run_block(gx, gy, 3, false, true,  w, s, nullptr);
    run_block(gx, gx, 4, true,  false, w, s, nullptr);
    run_block(gx, gy, 5, false, true,  w, s, (float*)d_out);
}

// round 6
// speedup vs baseline: 2.5227x; 2.5227x over previous
#include <cuda_runtime.h>
#include <math.h>
#include <stdint.h>

#define Bn   16
#define Ss   512
#define Dd   512
#define Hh   8
#define HSs  2
#define DKk  64
#define DFFf 2048
#define NGATE 6   // H - HS

// ---------------- scratch (device globals; no allocation allowed) ----------------
__device__ float g_y[Bn*Ss*Dd];
__device__ float g_x[Bn*Ss*Dd];
__device__ float g_qlin[Bn*Ss*Dd];
__device__ float g_v[Bn*Ss*Dd];
__device__ float g_ctx[Bn*Ss*Dd];
__device__ float g_tmp[Bn*Ss*Dd];
__device__ float g_ffn[Bn*Ss*DFFf];
__device__ float g_dyn[Bn*Ss*NGATE];
__device__ float g_rmask[Bn*Hh];

// ---------------- helpers ----------------
__device__ __forceinline__ float to_tf32(float x) {
    uint32_t u;
    asm("cvt.rna.tf32.f32 %0, %1;" : "=r"(u) : "f"(x));
    return __uint_as_float(u);
}

__device__ __forceinline__ void mma_tf32(float c[4], uint32_t a0, uint32_t a1,
                                         uint32_t a2, uint32_t a3,
                                         uint32_t b0, uint32_t b1) {
    asm volatile(
        "mma.sync.aligned.m16n8k8.row.col.f32.tf32.tf32.f32 "
        "{%0,%1,%2,%3}, {%4,%5,%6,%7}, {%8,%9}, {%0,%1,%2,%3};"
        : "+f"(c[0]), "+f"(c[1]), "+f"(c[2]), "+f"(c[3])
        : "r"(a0), "r"(a1), "r"(a2), "r"(a3), "r"(b0), "r"(b1));
}

__device__ __forceinline__ uint32_t smem_u32(const void* p) {
    uint32_t a;
    asm("{ .reg .u64 t; cvta.to.shared.u64 t, %1; cvt.u32.u64 %0, t; }"
        : "=r"(a) : "l"(p));
    return a;
}

__device__ __forceinline__ void cp_async16(uint32_t dst, const void* src) {
    asm volatile("cp.async.cg.shared.global [%0], [%1], 16;" :: "r"(dst), "l"(src));
}
__device__ __forceinline__ void cp_commit() {
    asm volatile("cp.async.commit_group;" ::: "memory");
}
template<int NN>
__device__ __forceinline__ void cp_wait() {
    asm volatile("cp.async.wait_group %0;" :: "n"(NN) : "memory");
}

// ---------------- cp.async 3-stage TF32 GEMM ----------------
// C = relu?( A[M,K] @ W[K,N] + bias ), row-major. BM=128, BN=128, BK=32.
// 256 threads (8 warps: 2M x 4N), warp tile 64x32.
// Loop: wait_group -> sync -> cp.async(kt+2 into stage (kt+2)%3) -> MMA(kt%3).
// The prefetch stage equals the stage read at kt-1; the sync orders those reads
// before the new writes land. ONE barrier per k-tile, no STS phase.
// Numerics: raw fp32 bits fed to tf32 MMA (mantissa truncation).
#define GBM 128
#define GBN 128
#define GBK 32
#define GLDA 36
#define GLDB 136
#define GSA (GBM * GLDA)          // 4608 floats
#define GSB (GBK * GLDB)          // 4352 floats
#define CA_SMEM (3 * (GSA + GSB) * 4)   // 107,520 bytes

__global__ void __launch_bounds__(256) gemm_ca_kernel(
    const float* __restrict__ A, const float* __restrict__ Bm,
    const float* __restrict__ bias, float* __restrict__ C,
    int K, int N, int relu)
{
    extern __shared__ __align__(16) float smg[];

    const int tid = threadIdx.x;
    const int warpId = tid >> 5;
    const int lane = tid & 31;
    const int grp = lane >> 2;
    const int tig = lane & 3;
    const int warpM = warpId & 1;
    const int warpN = warpId >> 1;
    const int row0 = blockIdx.y * GBM;
    const int col0 = blockIdx.x * GBN;

    const uint32_t sbase = smem_u32(smg);

    auto issue = [&](int kt) {
        const int st = kt % 3;
        const int k0 = kt * GBK;
        const uint32_t sA = sbase + (uint32_t)(st * (GSA + GSB)) * 4u;
        const uint32_t sB = sA + (uint32_t)GSA * 4u;
        #pragma unroll
        for (int i = 0; i < 4; i++) {
            int f4 = tid + i * 256;
            int r = f4 >> 3, kc = (f4 & 7) * 4;
            cp_async16(sA + (uint32_t)(r * GLDA + kc) * 4u,
                       &A[(long long)(row0 + r) * K + k0 + kc]);
        }
        #pragma unroll
        for (int i = 0; i < 4; i++) {
            int f4 = tid + i * 256;
            int kr = f4 >> 5, nc = (f4 & 31) * 4;
            cp_async16(sB + (uint32_t)(kr * GLDB + nc) * 4u,
                       &Bm[(long long)(k0 + kr) * N + col0 + nc]);
        }
        cp_commit();
    };

    float acc[4][4][4];
    #pragma unroll
    for (int mt = 0; mt < 4; mt++)
        #pragma unroll
        for (int nt = 0; nt < 4; nt++)
            #pragma unroll
            for (int q = 0; q < 4; q++) acc[mt][nt][q] = 0.f;

    const int KT = K / GBK;
    issue(0);
    if (KT > 1) issue(1);

    for (int kt = 0; kt < KT; kt++) {
        if (kt + 1 < KT) cp_wait<1>(); else cp_wait<0>();
        __syncthreads();
        if (kt + 2 < KT) issue(kt + 2);

        const float* As = smg + (kt % 3) * (GSA + GSB);
        const uint32_t* Asu = reinterpret_cast<const uint32_t*>(As);
        const uint32_t* Bsu = reinterpret_cast<const uint32_t*>(As + GSA);

        #pragma unroll
        for (int kk = 0; kk < GBK; kk += 8) {
            uint32_t af[4][4];
            #pragma unroll
            for (int mt = 0; mt < 4; mt++) {
                int base = (warpM * 64 + mt * 16 + grp) * GLDA + kk + tig;
                af[mt][0] = Asu[base];
                af[mt][1] = Asu[base + 8 * GLDA];
                af[mt][2] = Asu[base + 4];
                af[mt][3] = Asu[base + 8 * GLDA + 4];
            }
            uint32_t bf[4][2];
            #pragma unroll
            for (int nt = 0; nt < 4; nt++) {
                int base = (kk + tig) * GLDB + warpN * 32 + nt * 8 + grp;
                bf[nt][0] = Bsu[base];
                bf[nt][1] = Bsu[base + 4 * GLDB];
            }
            #pragma unroll
            for (int mt = 0; mt < 4; mt++)
                #pragma unroll
                for (int nt = 0; nt < 4; nt++)
                    mma_tf32(acc[mt][nt], af[mt][0], af[mt][1], af[mt][2], af[mt][3],
                             bf[nt][0], bf[nt][1]);
        }
    }

    #pragma unroll
    for (int mt = 0; mt < 4; mt++) {
        #pragma unroll
        for (int nt = 0; nt < 4; nt++) {
            int r0 = row0 + warpM * 64 + mt * 16 + grp;
            int cc = col0 + warpN * 32 + nt * 8 + tig * 2;
            float b0 = bias[cc], b1 = bias[cc + 1];
            float v0 = acc[mt][nt][0] + b0;
            float v1 = acc[mt][nt][1] + b1;
            float v2 = acc[mt][nt][2] + b0;
            float v3 = acc[mt][nt][3] + b1;
            if (relu) {
                v0 = fmaxf(v0, 0.f); v1 = fmaxf(v1, 0.f);
                v2 = fmaxf(v2, 0.f); v3 = fmaxf(v3, 0.f);
            }
            *(float2*)&C[(long long)r0 * N + cc]       = make_float2(v0, v1);
            *(float2*)&C[(long long)(r0 + 8) * N + cc] = make_float2(v2, v3);
        }
    }
}

// ---------------- fused flash attention (mma.sync TF32, rna cvt path) ----------------
#define FL_QS   0
#define FL_KP   (64*68)
#define FL_VS   (FL_KP + 64*68)
#define FL_REDM (FL_VS + 64*72)
#define FL_REDS (FL_REDM + 128)
#define FL_M    (FL_REDS + 128)
#define FL_L    (FL_M + 64)
#define FL_TOT  (FL_L + 64)
#define FL_BYTES (FL_TOT * 4)

__global__ void __launch_bounds__(256) flash_attn_kernel(
    const float* __restrict__ qlin, const float* __restrict__ v,
    const float* __restrict__ rmask, float* __restrict__ ctx, int mask_flag)
{
    extern __shared__ float sm[];
    float* Qs  = sm + FL_QS;
    float* KPs = sm + FL_KP;
    float* Vs  = sm + FL_VS;
    float* redm = sm + FL_REDM;
    float* reds = sm + FL_REDS;
    float* m_s  = sm + FL_M;
    float* l_s  = sm + FL_L;

    const int z = blockIdx.y;           // b*H + h
    const int b = z >> 3, h = z & 7;
    const int q0 = blockIdx.x * 64;
    const float* Qg = qlin + (long long)b * Ss * Dd + h * 64;
    const float* Vg = v    + (long long)b * Ss * Dd + h * 64;

    const int tid = threadIdx.x;
    const int warpId = tid >> 5, lane = tid & 31;
    const int grp = lane >> 2, tig = lane & 3;
    const int warpM = warpId >> 1, warpN = warpId & 1;
    const int row_a = warpM * 16 + grp;

    #pragma unroll
    for (int i = 0; i < 4; i++) {
        int id = tid + i * 256;
        int r = id >> 4, c4 = (id & 15) * 4;
        float4 q4 = *(const float4*)&Qg[(long long)(q0 + r) * Dd + c4];
        q4.x = to_tf32(q4.x * 0.125f); q4.y = to_tf32(q4.y * 0.125f);
        q4.z = to_tf32(q4.z * 0.125f); q4.w = to_tf32(q4.w * 0.125f);
        *(float4*)&Qs[r * 68 + c4] = q4;
    }
    if (tid < 64) { m_s[tid] = -1e30f; l_s[tid] = 0.f; }

    float Oa[4][4];
    #pragma unroll
    for (int nt = 0; nt < 4; nt++)
        #pragma unroll
        for (int q = 0; q < 4; q++) Oa[nt][q] = 0.f;

    const uint32_t* Qu  = reinterpret_cast<const uint32_t*>(Qs);
    const uint32_t* KPu = reinterpret_cast<const uint32_t*>(KPs);
    const uint32_t* Vu  = reinterpret_cast<const uint32_t*>(Vs);

    const int nTiles = blockIdx.x + 1;

    for (int kt = 0; kt < nTiles; kt++) {
        const int k0 = kt * 64;
        #pragma unroll
        for (int i = 0; i < 4; i++) {
            int id = tid + i * 256;
            int r = id >> 4, c4 = (id & 15) * 4;
            float4 k4 = *(const float4*)&Qg[(long long)(k0 + r) * Dd + c4];
            k4.x = to_tf32(k4.x); k4.y = to_tf32(k4.y);
            k4.z = to_tf32(k4.z); k4.w = to_tf32(k4.w);
            *(float4*)&KPs[r * 68 + c4] = k4;
            float4 v4 = *(const float4*)&Vg[(long long)(k0 + r) * Dd + c4];
            v4.x = to_tf32(v4.x); v4.y = to_tf32(v4.y);
            v4.z = to_tf32(v4.z); v4.w = to_tf32(v4.w);
            *(float4*)&Vs[r * 72 + c4] = v4;
        }
        __syncthreads();

        float scf[4][4];
        #pragma unroll
        for (int nt = 0; nt < 4; nt++)
            #pragma unroll
            for (int q = 0; q < 4; q++) scf[nt][q] = 0.f;

        #pragma unroll
        for (int kk = 0; kk < 64; kk += 8) {
            uint32_t a0 = Qu[(row_a)     * 68 + kk + tig];
            uint32_t a1 = Qu[(row_a + 8) * 68 + kk + tig];
            uint32_t a2 = Qu[(row_a)     * 68 + kk + tig + 4];
            uint32_t a3 = Qu[(row_a + 8) * 68 + kk + tig + 4];
            #pragma unroll
            for (int nt = 0; nt < 4; nt++) {
                int nc = warpN * 32 + nt * 8 + grp;
                uint32_t b0 = KPu[nc * 68 + kk + tig];
                uint32_t b1 = KPu[nc * 68 + kk + tig + 4];
                mma_tf32(scf[nt], a0, a1, a2, a3, b0, b1);
            }
        }

        if (kt == nTiles - 1) {
            int iA = q0 + row_a, iB = iA + 8;
            int limA = iA + (mask_flag ? 1 : 0);
            int limB = iB + (mask_flag ? 1 : 0);
            #pragma unroll
            for (int nt = 0; nt < 4; nt++) {
                int j0 = k0 + warpN * 32 + nt * 8 + tig * 2;
                if (j0     >= limA) scf[nt][0] = -1e30f;
                if (j0 + 1 >= limA) scf[nt][1] = -1e30f;
                if (j0     >= limB) scf[nt][2] = -1e30f;
                if (j0 + 1 >= limB) scf[nt][3] = -1e30f;
            }
        }

        float mA_old = m_s[row_a], mB_old = m_s[row_a + 8];

        float tmA = -1e30f, tmB = -1e30f;
        #pragma unroll
        for (int nt = 0; nt < 4; nt++) {
            tmA = fmaxf(tmA, fmaxf(scf[nt][0], scf[nt][1]));
            tmB = fmaxf(tmB, fmaxf(scf[nt][2], scf[nt][3]));
        }
        tmA = fmaxf(tmA, __shfl_xor_sync(0xffffffffu, tmA, 1));
        tmA = fmaxf(tmA, __shfl_xor_sync(0xffffffffu, tmA, 2));
        tmB = fmaxf(tmB, __shfl_xor_sync(0xffffffffu, tmB, 1));
        tmB = fmaxf(tmB, __shfl_xor_sync(0xffffffffu, tmB, 2));
        if (tig == 0) {
            redm[warpN * 64 + row_a]     = tmA;
            redm[warpN * 64 + row_a + 8] = tmB;
        }
        __syncthreads();

        float mA = fmaxf(mA_old, fmaxf(redm[row_a],     redm[64 + row_a]));
        float mB = fmaxf(mB_old, fmaxf(redm[row_a + 8], redm[64 + row_a + 8]));
        float alA = __expf(mA_old - mA);
        float alB = __expf(mB_old - mB);

        float psA = 0.f, psB = 0.f;
        #pragma unroll
        for (int nt = 0; nt < 4; nt++) {
            float p0 = __expf(scf[nt][0] - mA);
            float p1 = __expf(scf[nt][1] - mA);
            float p2 = __expf(scf[nt][2] - mB);
            float p3 = __expf(scf[nt][3] - mB);
            psA += p0 + p1; psB += p2 + p3;
            int nc = warpN * 32 + nt * 8 + tig * 2;
            KPs[row_a * 68 + nc]           = to_tf32(p0);
            KPs[row_a * 68 + nc + 1]       = to_tf32(p1);
            KPs[(row_a + 8) * 68 + nc]     = to_tf32(p2);
            KPs[(row_a + 8) * 68 + nc + 1] = to_tf32(p3);
            Oa[nt][0] *= alA; Oa[nt][1] *= alA;
            Oa[nt][2] *= alB; Oa[nt][3] *= alB;
        }
        psA += __shfl_xor_sync(0xffffffffu, psA, 1);
        psA += __shfl_xor_sync(0xffffffffu, psA, 2);
        psB += __shfl_xor_sync(0xffffffffu, psB, 1);
        psB += __shfl_xor_sync(0xffffffffu, psB, 2);
        if (tig == 0) {
            reds[warpN * 64 + row_a]     = psA;
            reds[warpN * 64 + row_a + 8] = psB;
        }
        if (warpN == 0 && tig == 0) {
            m_s[row_a]     = mA;
            m_s[row_a + 8] = mB;
        }
        __syncthreads();

        if (warpN == 0 && tig == 0) {
            l_s[row_a]     = alA * l_s[row_a]     + reds[row_a]     + reds[64 + row_a];
            l_s[row_a + 8] = alB * l_s[row_a + 8] + reds[row_a + 8] + reds[64 + row_a + 8];
        }

        #pragma unroll
        for (int kk = 0; kk < 64; kk += 8) {
            uint32_t a0 = KPu[(row_a)     * 68 + kk + tig];
            uint32_t a1 = KPu[(row_a + 8) * 68 + kk + tig];
            uint32_t a2 = KPu[(row_a)     * 68 + kk + tig + 4];
            uint32_t a3 = KPu[(row_a + 8) * 68 + kk + tig + 4];
            #pragma unroll
            for (int nt = 0; nt < 4; nt++) {
                int nc = warpN * 32 + nt * 8 + grp;
                uint32_t b0 = Vu[(kk + tig)     * 72 + nc];
                uint32_t b1 = Vu[(kk + tig + 4) * 72 + nc];
                mma_tf32(Oa[nt], a0, a1, a2, a3, b0, b1);
            }
        }
        __syncthreads();
    }

    float rm = rmask[z];
    float invA = rm / l_s[row_a];
    float invB = rm / l_s[row_a + 8];
    #pragma unroll
    for (int nt = 0; nt < 4; nt++) {
        int col = h * 64 + warpN * 32 + nt * 8 + tig * 2;
        long long oA = ((long long)b * Ss + q0 + row_a) * Dd + col;
        long long oB = oA + 8LL * Dd;
        *(float2*)&ctx[oA] = make_float2(Oa[nt][0] * invA, Oa[nt][1] * invA);
        *(float2*)&ctx[oB] = make_float2(Oa[nt][2] * invB, Oa[nt][3] * invB);
    }
}

// ---------------- pad row 0 ----------------
__global__ void pad_row_kernel(const float* __restrict__ v, const float* __restrict__ rmask,
                               float* __restrict__ ctx)
{
    int z = blockIdx.x;                 // B*H
    int b = z >> 3, h = z & 7;
    int tid = threadIdx.x;              // 256: (chunk 0..3) x (d 0..63)
    int d = tid & 63, chunk = tid >> 6;
    const float* Vg = v + (long long)b * Ss * Dd + h * 64 + d;
    float s = 0.f;
    for (int j = chunk * 128; j < (chunk + 1) * 128; j++)
        s += Vg[(long long)j * Dd];
    __shared__ float red[256];
    red[tid] = s;
    __syncthreads();
    if (tid < 64) {
        float t = red[tid] + red[tid + 64] + red[tid + 128] + red[tid + 192];
        ctx[(long long)b * Ss * Dd + h * 64 + tid] = t * (1.0f / Ss) * rmask[z];
    }
}

// ---------------- residual + LayerNorm ----------------
__global__ void add_ln_kernel(const float* __restrict__ resid, const float* __restrict__ delta,
                              const float* __restrict__ g, const float* __restrict__ b,
                              float* __restrict__ out)
{
    long long base = (long long)blockIdx.x * Dd;
    int tid = threadIdx.x;
    float v0 = resid[base + tid]       + delta[base + tid];
    float v1 = resid[base + tid + 256] + delta[base + tid + 256];
    float s  = v0 + v1;
    float sq = v0 * v0 + v1 * v1;

    __shared__ float rs[8], rq[8];
    #pragma unroll
    for (int o = 16; o; o >>= 1) {
        s  += __shfl_xor_sync(0xffffffffu, s,  o);
        sq += __shfl_xor_sync(0xffffffffu, sq, o);
    }
    if ((tid & 31) == 0) { rs[tid >> 5] = s; rq[tid >> 5] = sq; }
    __syncthreads();
    s = 0.f; sq = 0.f;
    #pragma unroll
    for (int w2 = 0; w2 < 8; w2++) { s += rs[w2]; sq += rq[w2]; }

    float mu   = s * (1.0f / Dd);
    float var  = sq * (1.0f / Dd) - mu * mu;
    float rstd = rsqrtf(var + 1e-5f);
    out[base + tid]       = g[tid]       * ((v0 - mu) * rstd) + b[tid];
    out[base + tid + 256] = g[tid + 256] * ((v1 - mu) * rstd) + b[tid + 256];
}

// ---------------- head-routing gate: one warp per token ----------------
__global__ void gating_kernel(const float* __restrict__ qlin, const float* __restrict__ wg,
                              float* __restrict__ dyn)
{
    int gw   = (int)((blockIdx.x * blockDim.x + threadIdx.x) >> 5);
    int lane = threadIdx.x & 31;
    if (gw >= Bn * Ss) return;
    const float* q = qlin + (long long)gw * Dd;

    float acc[NGATE];
    #pragma unroll
    for (int g2 = 0; g2 < NGATE; g2++) acc[g2] = 0.f;
    for (int d = lane; d < Dd; d += 32) {
        float qv = q[d];
        const float* w = wg + d * NGATE;
        #pragma unroll
        for (int g2 = 0; g2 < NGATE; g2++) acc[g2] += qv * w[g2];
    }
    #pragma unroll
    for (int g2 = 0; g2 < NGATE; g2++)
        #pragma unroll
        for (int o = 16; o; o >>= 1) acc[g2] += __shfl_xor_sync(0xffffffffu, acc[g2], o);

    if (lane == 0) {
        int i1 = 0;
        #pragma unroll
        for (int g2 = 1; g2 < NGATE; g2++) if (acc[g2] > acc[i1]) i1 = g2;
        int i2 = (i1 == 0) ? 1 : 0;
        #pragma unroll
        for (int g2 = 0; g2 < NGATE; g2++)
            if (g2 != i1 && acc[g2] > acc[i2]) i2 = g2;

        float mx = acc[i1], sum = 0.f, e[NGATE];
        #pragma unroll
        for (int g2 = 0; g2 < NGATE; g2++) { e[g2] = expf(acc[g2] - mx); sum += e[g2]; }
        float inv = 1.0f / sum;
        #pragma unroll
        for (int g2 = 0; g2 < NGATE; g2++)
            dyn[(long long)gw * NGATE + g2] = (g2 == i1 || g2 == i2) ? e[g2] * inv : 0.f;
    }
}

// ---------------- rmask[b,h] ----------------
__global__ void rmask_kernel(const float* __restrict__ dyn, float* __restrict__ rmask)
{
    int z = blockIdx.x;             // B*H
    int b = z / Hh, h = z % Hh;
    int tid = threadIdx.x;          // 256
    if (h < HSs) { if (tid == 0) rmask[z] = 1.f; return; }
    int g = h - HSs;
    float v = dyn[((long long)(b * Ss + tid))       * NGATE + g]
            + dyn[((long long)(b * Ss + tid + 256)) * NGATE + g];
    __shared__ float rs[8];
    #pragma unroll
    for (int o = 16; o; o >>= 1) v += __shfl_xor_sync(0xffffffffu, v, o);
    if ((tid & 31) == 0) rs[tid >> 5] = v;
    __syncthreads();
    if (tid == 0) {
        float t = 0.f;
        #pragma unroll
        for (int w2 = 0; w2 < 8; w2++) t += rs[w2];
        rmask[z] = t * (1.0f / Ss);
    }
}

// ---------------- host orchestration ----------------
struct Wts {
    const float *wq, *bq, *wv, *bv, *wo, *bo, *wg;
    const float *ln1g, *ln1b, *fw1, *fb1, *fw2, *fb2, *ln2g, *ln2b;
};
struct Scr {
    float *qlin, *v, *ctx, *tmp, *ffn, *dyn, *rmask;
};

static void gemm_ca(const float* A, const float* Bm, const float* bias, float* C,
                    int M, int N, int K, int relu)
{
    dim3 grid(N / GBN, M / GBM);
    gemm_ca_kernel<<<grid, 256, CA_SMEM>>>(A, Bm, bias, C, K, N, relu);
}

static void run_block(float* xq, float* xv, int layer, bool mask_flag, bool apply_pos,
                      const Wts& w, const Scr& s, float* finalOut)
{
    const int M = Bn * Ss;
    const long long DD = (long long)Dd * Dd;

    gemm_ca(xq, w.wq + layer * DD, w.bq + layer * Dd, s.qlin, M, Dd, Dd, 0);
    gemm_ca(xv, w.wv + layer * DD, w.bv + layer * Dd, s.v,    M, Dd, Dd, 0);

    gating_kernel<<<(Bn * Ss * 32 + 255) / 256, 256>>>(
        s.qlin, w.wg + (long long)layer * Dd * NGATE, s.dyn);
    rmask_kernel<<<Bn * Hh, 256>>>(s.dyn, s.rmask);

    flash_attn_kernel<<<dim3(Ss / 64, Bn * Hh), 256, FL_BYTES>>>(
        s.qlin, s.v, s.rmask, s.ctx, mask_flag ? 1 : 0);
    pad_row_kernel<<<Bn * Hh, 256>>>(s.v, s.rmask, s.ctx);

    gemm_ca(s.ctx, w.wo + layer * DD, w.bo + layer * Dd, s.tmp, M, Dd, Dd, 0);

    add_ln_kernel<<<M, 256>>>(xq, s.tmp, w.ln1g + layer * Dd, w.ln1b + layer * Dd, xq);

    if (apply_pos) {
        gemm_ca(xq, w.fw1 + (long long)layer * Dd * DFFf, w.fb1 + layer * DFFf, s.ffn,
                M, DFFf, Dd, 1);
        gemm_ca(s.ffn, w.fw2 + (long long)layer * DFFf * Dd, w.fb2 + layer * Dd, s.tmp,
                M, Dd, DFFf, 0);
        float* out2 = finalOut ? finalOut : xq;
        add_ln_kernel<<<M, 256>>>(xq, s.tmp, w.ln2g + layer * Dd, w.ln2b + layer * Dd, out2);
    }
}

extern "C" void kernel_launch(void* const* d_in, const int* in_sizes, int n_in,
                              void* d_out, int out_size)
{
    const float* question    = (const float*)d_in[0];
    const float* interaction = (const float*)d_in[1];
    Wts w;
    w.wq   = (const float*)d_in[2];  w.bq   = (const float*)d_in[3];
    w.wv   = (const float*)d_in[4];  w.bv   = (const float*)d_in[5];
    w.wo   = (const float*)d_in[6];  w.bo   = (const float*)d_in[7];
    w.wg   = (const float*)d_in[8];
    w.ln1g = (const float*)d_in[9];  w.ln1b = (const float*)d_in[10];
    w.fw1  = (const float*)d_in[11]; w.fb1  = (const float*)d_in[12];
    w.fw2  = (const float*)d_in[13]; w.fb2  = (const float*)d_in[14];
    w.ln2g = (const float*)d_in[15]; w.ln2b = (const float*)d_in[16];

    cudaFuncSetAttribute(flash_attn_kernel,
                         cudaFuncAttributeMaxDynamicSharedMemorySize, FL_BYTES);
    cudaFuncSetAttribute(gemm_ca_kernel,
                         cudaFuncAttributeMaxDynamicSharedMemorySize, CA_SMEM);

    float *gx, *gy;
    Scr s;
    cudaGetSymbolAddress((void**)&gx,      g_x);
    cudaGetSymbolAddress((void**)&gy,      g_y);
    cudaGetSymbolAddress((void**)&s.qlin,  g_qlin);
    cudaGetSymbolAddress((void**)&s.v,     g_v);
    cudaGetSymbolAddress((void**)&s.ctx,   g_ctx);
    cudaGetSymbolAddress((void**)&s.tmp,   g_tmp);
    cudaGetSymbolAddress((void**)&s.ffn,   g_ffn);
    cudaGetSymbolAddress((void**)&s.dyn,   g_dyn);
    cudaGetSymbolAddress((void**)&s.rmask, g_rmask);

    size_t bytes = (size_t)Bn * Ss * Dd * sizeof(float);
    cudaMemcpyAsync(gy, interaction, bytes, cudaMemcpyDeviceToDevice);
    cudaMemcpyAsync(gx, question,    bytes, cudaMemcpyDeviceToDevice);

    // knowledge encoder
    run_block(gy, gy, 0, true,  false, w, s, nullptr);
    run_block(gy, gy, 1, true,  false, w, s, nullptr);
    // question encoder
    run_block(gx, gx, 2, true,  false, w, s, nullptr);
    run_block(gx, gy, 3, false, true,  w, s, nullptr);
    run_block(gx, gx, 4, true,  false, w, s, nullptr);
    run_block(gx, gy, 5, false, true,  w, s, (float*)d_out);
}

// round 8
// speedup vs baseline: 3.2660x; 1.2946x over previous
#include <cuda_runtime.h>
#include <cuda_fp16.h>
#include <math.h>
#include <stdint.h>

#define Bn   16
#define Ss   512
#define Dd   512
#define Hh   8
#define HSs  2
#define DKk  64
#define DFFf 2048
#define NGATE 6   // H - HS

// ---------------- scratch (device globals; no allocation allowed) ----------------
__device__ float g_y[Bn*Ss*Dd];
__device__ float g_x[Bn*Ss*Dd];
__device__ float g_qlin[Bn*Ss*Dd];
__device__ float g_v[Bn*Ss*Dd];
__device__ float g_tmp[Bn*Ss*Dd];
__device__ float g_dyn[Bn*Ss*NGATE];
__device__ float g_rmask[Bn*Hh];
// half mirrors / operands
__device__ __half g_xh[Bn*Ss*Dd];
__device__ __half g_yh[Bn*Ss*Dd];
__device__ __half g_ctxh[Bn*Ss*Dd];
__device__ __half g_ffnh[Bn*Ss*DFFf];
// transposed half weights
__device__ __half g_wqh[6*Dd*Dd];
__device__ __half g_wvh[6*Dd*Dd];
__device__ __half g_woh[6*Dd*Dd];
__device__ __half g_fw1h[6*Dd*DFFf];   // per layer: [DFF][D]
__device__ __half g_fw2h[6*DFFf*Dd];   // per layer: [D][DFF]

// ---------------- helpers ----------------
__device__ __forceinline__ float to_tf32(float x) {
    uint32_t u;
    asm("cvt.rna.tf32.f32 %0, %1;" : "=r"(u) : "f"(x));
    return __uint_as_float(u);
}

__device__ __forceinline__ void mma_tf32(float c[4], uint32_t a0, uint32_t a1,
                                         uint32_t a2, uint32_t a3,
                                         uint32_t b0, uint32_t b1) {
    asm volatile(
        "mma.sync.aligned.m16n8k8.row.col.f32.tf32.tf32.f32 "
        "{%0,%1,%2,%3}, {%4,%5,%6,%7}, {%8,%9}, {%0,%1,%2,%3};"
        : "+f"(c[0]), "+f"(c[1]), "+f"(c[2]), "+f"(c[3])
        : "r"(a0), "r"(a1), "r"(a2), "r"(a3), "r"(b0), "r"(b1));
}

__device__ __forceinline__ void mma_f16(float c[4], uint32_t a0, uint32_t a1,
                                        uint32_t a2, uint32_t a3,
                                        uint32_t b0, uint32_t b1) {
    asm volatile(
        "mma.sync.aligned.m16n8k16.row.col.f32.f16.f16.f32 "
        "{%0,%1,%2,%3}, {%4,%5,%6,%7}, {%8,%9}, {%0,%1,%2,%3};"
        : "+f"(c[0]), "+f"(c[1]), "+f"(c[2]), "+f"(c[3])
        : "r"(a0), "r"(a1), "r"(a2), "r"(a3), "r"(b0), "r"(b1));
}

__device__ __forceinline__ uint32_t smem_u32(const void* p) {
    uint32_t a;
    asm("{ .reg .u64 t; cvta.to.shared.u64 t, %1; cvt.u32.u64 %0, t; }"
        : "=r"(a) : "l"(p));
    return a;
}

__device__ __forceinline__ void cp_async16(uint32_t dst, const void* src) {
    asm volatile("cp.async.cg.shared.global [%0], [%1], 16;" :: "r"(dst), "l"(src));
}
__device__ __forceinline__ void cp_commit() {
    asm volatile("cp.async.commit_group;" ::: "memory");
}
template<int NN>
__device__ __forceinline__ void cp_wait() {
    asm volatile("cp.async.wait_group %0;" :: "n"(NN) : "memory");
}

// ---------------- weight convert + transpose: fp32 [R][C] -> half [C][R] ----------------
__global__ void transp_h_kernel(const float* __restrict__ in, __half* __restrict__ out,
                                int R, int C, long long inStride, long long outStride)
{
    __shared__ float t[32][33];
    const float* ip = in + blockIdx.z * inStride;
    __half* op = out + blockIdx.z * outStride;
    int c0 = blockIdx.x * 32, r0 = blockIdx.y * 32;
    int x = threadIdx.x, y0 = threadIdx.y;   // (32,8)
    #pragma unroll
    for (int i = 0; i < 32; i += 8)
        t[y0 + i][x] = ip[(long long)(r0 + y0 + i) * C + c0 + x];
    __syncthreads();
    #pragma unroll
    for (int i = 0; i < 32; i += 8)
        op[(long long)(c0 + y0 + i) * R + r0 + x] = __float2half_rn(t[x][y0 + i]);
}

// ---------------- embeddings fp32 -> half ----------------
__global__ void f2h_kernel(const float* __restrict__ a, __half* __restrict__ ah,
                           const float* __restrict__ b, __half* __restrict__ bh, int n)
{
    int i = blockIdx.x * blockDim.x + threadIdx.x;
    if (i < n) {
        ah[i] = __float2half_rn(a[i]);
        bh[i] = __float2half_rn(b[i]);
    }
}

// ---------------- cp.async 3-stage FP16 GEMM ----------------
// C = relu?( A[M,K]h @ Bt[N,K]h^T + bias ), A row-major halves, Bt = transposed
// weight (n-major, k contiguous). BM=BN=128, BK=64. 256 thr, 8 warps 2Mx4N,
// warp tile 64x32, mma m16n8k16. OM: 0 = fp32 out, 1 = half out.
#define HBM 128
#define HBN 128
#define HBK 64
#define HLDA 72                    // halves per padded row (64 + 8)
#define HSA (HBM * HLDA)           // halves = 9216
#define HSTAGE (2 * HSA)           // A + B halves = 18432
#define H_SMEM (3 * HSTAGE * 2)    // bytes = 110592

template<int OM>
__global__ void __launch_bounds__(256) gemm_h_kernel(
    const __half* __restrict__ A, const __half* __restrict__ Bt,
    const float* __restrict__ bias, float* __restrict__ Cf, __half* __restrict__ Ch,
    int K, int N, int relu)
{
    extern __shared__ __align__(16) __half smh[];

    const int tid = threadIdx.x;
    const int warpId = tid >> 5;
    const int lane = tid & 31;
    const int grp = lane >> 2;
    const int tig = lane & 3;
    const int warpM = warpId & 1;
    const int warpN = warpId >> 1;
    const int row0 = blockIdx.y * HBM;
    const int col0 = blockIdx.x * HBN;

    const uint32_t sbase = smem_u32(smh);

    // tile = 128 rows x 64 halves = 1024 16B-chunks per operand -> 4 iters x 256 thr
    auto issue = [&](int kt) {
        const int st = kt % 3;
        const int k0 = kt * HBK;
        const uint32_t sA = sbase + (uint32_t)(st * HSTAGE) * 2u;
        const uint32_t sB = sA + (uint32_t)HSA * 2u;
        #pragma unroll
        for (int i = 0; i < 4; i++) {
            int f4 = tid + i * 256;
            int r = f4 >> 3, c8 = (f4 & 7) * 8;
            cp_async16(sA + (uint32_t)(r * HLDA + c8) * 2u,
                       &A[(long long)(row0 + r) * K + k0 + c8]);
        }
        #pragma unroll
        for (int i = 0; i < 4; i++) {
            int f4 = tid + i * 256;
            int n = f4 >> 3, c8 = (f4 & 7) * 8;
            cp_async16(sB + (uint32_t)(n * HLDA + c8) * 2u,
                       &Bt[(long long)(col0 + n) * K + k0 + c8]);
        }
        cp_commit();
    };

    float acc[4][4][4];
    #pragma unroll
    for (int mt = 0; mt < 4; mt++)
        #pragma unroll
        for (int nt = 0; nt < 4; nt++)
            #pragma unroll
            for (int q = 0; q < 4; q++) acc[mt][nt][q] = 0.f;

    const int KT = K / HBK;
    issue(0);
    if (KT > 1) issue(1);

    for (int kt = 0; kt < KT; kt++) {
        if (kt + 1 < KT) cp_wait<1>(); else cp_wait<0>();
        __syncthreads();
        if (kt + 2 < KT) issue(kt + 2);

        const uint32_t* Asu = reinterpret_cast<const uint32_t*>(smh + (kt % 3) * HSTAGE);
        const uint32_t* Bsu = Asu + HSA / 2;    // word offset

        #pragma unroll
        for (int kk = 0; kk < 4; kk++) {        // 4 steps of k16
            const int kw = kk * 8;              // word offset within row
            uint32_t af[4][4];
            #pragma unroll
            for (int mt = 0; mt < 4; mt++) {
                int base = (warpM * 64 + mt * 16 + grp) * 36 + kw + tig;
                af[mt][0] = Asu[base];
                af[mt][1] = Asu[base + 8 * 36];
                af[mt][2] = Asu[base + 4];
                af[mt][3] = Asu[base + 8 * 36 + 4];
            }
            uint32_t bf[4][2];
            #pragma unroll
            for (int nt = 0; nt < 4; nt++) {
                int base = (warpN * 32 + nt * 8 + grp) * 36 + kw + tig;
                bf[nt][0] = Bsu[base];
                bf[nt][1] = Bsu[base + 4];
            }
            #pragma unroll
            for (int mt = 0; mt < 4; mt++)
                #pragma unroll
                for (int nt = 0; nt < 4; nt++)
                    mma_f16(acc[mt][nt], af[mt][0], af[mt][1], af[mt][2], af[mt][3],
                            bf[nt][0], bf[nt][1]);
        }
    }

    #pragma unroll
    for (int mt = 0; mt < 4; mt++) {
        #pragma unroll
        for (int nt = 0; nt < 4; nt++) {
            int r0 = row0 + warpM * 64 + mt * 16 + grp;
            int cc = col0 + warpN * 32 + nt * 8 + tig * 2;
            float b0 = bias[cc], b1 = bias[cc + 1];
            float v0 = acc[mt][nt][0] + b0;
            float v1 = acc[mt][nt][1] + b1;
            float v2 = acc[mt][nt][2] + b0;
            float v3 = acc[mt][nt][3] + b1;
            if (relu) {
                v0 = fmaxf(v0, 0.f); v1 = fmaxf(v1, 0.f);
                v2 = fmaxf(v2, 0.f); v3 = fmaxf(v3, 0.f);
            }
            if (OM == 0) {
                *(float2*)&Cf[(long long)r0 * N + cc]       = make_float2(v0, v1);
                *(float2*)&Cf[(long long)(r0 + 8) * N + cc] = make_float2(v2, v3);
            } else {
                *(__half2*)&Ch[(long long)r0 * N + cc]       = __floats2half2_rn(v0, v1);
                *(__half2*)&Ch[(long long)(r0 + 8) * N + cc] = __floats2half2_rn(v2, v3);
            }
        }
    }
}

// ---------------- fused flash attention (mma.sync TF32, half ctx out) ----------------
#define FL_QS   0
#define FL_KP   (64*68)
#define FL_VS   (FL_KP + 64*68)
#define FL_REDM (FL_VS + 64*72)
#define FL_REDS (FL_REDM + 128)
#define FL_M    (FL_REDS + 128)
#define FL_L    (FL_M + 64)
#define FL_TOT  (FL_L + 64)
#define FL_BYTES (FL_TOT * 4)

__global__ void __launch_bounds__(256) flash_attn_kernel(
    const float* __restrict__ qlin, const float* __restrict__ v,
    const float* __restrict__ rmask, __half* __restrict__ ctxh, int mask_flag)
{
    extern __shared__ float sm[];
    float* Qs  = sm + FL_QS;
    float* KPs = sm + FL_KP;
    float* Vs  = sm + FL_VS;
    float* redm = sm + FL_REDM;
    float* reds = sm + FL_REDS;
    float* m_s  = sm + FL_M;
    float* l_s  = sm + FL_L;

    const int z = blockIdx.y;           // b*H + h
    const int b = z >> 3, h = z & 7;
    const int q0 = blockIdx.x * 64;
    const float* Qg = qlin + (long long)b * Ss * Dd + h * 64;
    const float* Vg = v    + (long long)b * Ss * Dd + h * 64;

    const int tid = threadIdx.x;
    const int warpId = tid >> 5, lane = tid & 31;
    const int grp = lane >> 2, tig = lane & 3;
    const int warpM = warpId >> 1, warpN = warpId & 1;
    const int row_a = warpM * 16 + grp;

    #pragma unroll
    for (int i = 0; i < 4; i++) {
        int id = tid + i * 256;
        int r = id >> 4, c4 = (id & 15) * 4;
        float4 q4 = *(const float4*)&Qg[(long long)(q0 + r) * Dd + c4];
        q4.x = to_tf32(q4.x * 0.125f); q4.y = to_tf32(q4.y * 0.125f);
        q4.z = to_tf32(q4.z * 0.125f); q4.w = to_tf32(q4.w * 0.125f);
        *(float4*)&Qs[r * 68 + c4] = q4;
    }
    if (tid < 64) { m_s[tid] = -1e30f; l_s[tid] = 0.f; }

    float Oa[4][4];
    #pragma unroll
    for (int nt = 0; nt < 4; nt++)
        #pragma unroll
        for (int q = 0; q < 4; q++) Oa[nt][q] = 0.f;

    const uint32_t* Qu  = reinterpret_cast<const uint32_t*>(Qs);
    const uint32_t* KPu = reinterpret_cast<const uint32_t*>(KPs);
    const uint32_t* Vu  = reinterpret_cast<const uint32_t*>(Vs);

    const int nTiles = blockIdx.x + 1;

    for (int kt = 0; kt < nTiles; kt++) {
        const int k0 = kt * 64;
        #pragma unroll
        for (int i = 0; i < 4; i++) {
            int id = tid + i * 256;
            int r = id >> 4, c4 = (id & 15) * 4;
            float4 k4 = *(const float4*)&Qg[(long long)(k0 + r) * Dd + c4];
            k4.x = to_tf32(k4.x); k4.y = to_tf32(k4.y);
            k4.z = to_tf32(k4.z); k4.w = to_tf32(k4.w);
            *(float4*)&KPs[r * 68 + c4] = k4;
            float4 v4 = *(const float4*)&Vg[(long long)(k0 + r) * Dd + c4];
            v4.x = to_tf32(v4.x); v4.y = to_tf32(v4.y);
            v4.z = to_tf32(v4.z); v4.w = to_tf32(v4.w);
            *(float4*)&Vs[r * 72 + c4] = v4;
        }
        __syncthreads();

        float scf[4][4];
        #pragma unroll
        for (int nt = 0; nt < 4; nt++)
            #pragma unroll
            for (int q = 0; q < 4; q++) scf[nt][q] = 0.f;

        #pragma unroll
        for (int kk = 0; kk < 64; kk += 8) {
            uint32_t a0 = Qu[(row_a)     * 68 + kk + tig];
            uint32_t a1 = Qu[(row_a + 8) * 68 + kk + tig];
            uint32_t a2 = Qu[(row_a)     * 68 + kk + tig + 4];
            uint32_t a3 = Qu[(row_a + 8) * 68 + kk + tig + 4];
            #pragma unroll
            for (int nt = 0; nt < 4; nt++) {
                int nc = warpN * 32 + nt * 8 + grp;
                uint32_t b0 = KPu[nc * 68 + kk + tig];
                uint32_t b1 = KPu[nc * 68 + kk + tig + 4];
                mma_tf32(scf[nt], a0, a1, a2, a3, b0, b1);
            }
        }

        if (kt == nTiles - 1) {
            int iA = q0 + row_a, iB = iA + 8;
            int limA = iA + (mask_flag ? 1 : 0);
            int limB = iB + (mask_flag ? 1 : 0);
            #pragma unroll
            for (int nt = 0; nt < 4; nt++) {
                int j0 = k0 + warpN * 32 + nt * 8 + tig * 2;
                if (j0     >= limA) scf[nt][0] = -1e30f;
                if (j0 + 1 >= limA) scf[nt][1] = -1e30f;
                if (j0     >= limB) scf[nt][2] = -1e30f;
                if (j0 + 1 >= limB) scf[nt][3] = -1e30f;
            }
        }

        float mA_old = m_s[row_a], mB_old = m_s[row_a + 8];

        float tmA = -1e30f, tmB = -1e30f;
        #pragma unroll
        for (int nt = 0; nt < 4; nt++) {
            tmA = fmaxf(tmA, fmaxf(scf[nt][0], scf[nt][1]));
            tmB = fmaxf(tmB, fmaxf(scf[nt][2], scf[nt][3]));
        }
        tmA = fmaxf(tmA, __shfl_xor_sync(0xffffffffu, tmA, 1));
        tmA = fmaxf(tmA, __shfl_xor_sync(0xffffffffu, tmA, 2));
        tmB = fmaxf(tmB, __shfl_xor_sync(0xffffffffu, tmB, 1));
        tmB = fmaxf(tmB, __shfl_xor_sync(0xffffffffu, tmB, 2));
        if (tig == 0) {
            redm[warpN * 64 + row_a]     = tmA;
            redm[warpN * 64 + row_a + 8] = tmB;
        }
        __syncthreads();

        float mA = fmaxf(mA_old, fmaxf(redm[row_a],     redm[64 + row_a]));
        float mB = fmaxf(mB_old, fmaxf(redm[row_a + 8], redm[64 + row_a + 8]));
        float alA = __expf(mA_old - mA);
        float alB = __expf(mB_old - mB);

        float psA = 0.f, psB = 0.f;
        #pragma unroll
        for (int nt = 0; nt < 4; nt++) {
            float p0 = __expf(scf[nt][0] - mA);
            float p1 = __expf(scf[nt][1] - mA);
            float p2 = __expf(scf[nt][2] - mB);
            float p3 = __expf(scf[nt][3] - mB);
            psA += p0 + p1; psB += p2 + p3;
            int nc = warpN * 32 + nt * 8 + tig * 2;
            KPs[row_a * 68 + nc]           = to_tf32(p0);
            KPs[row_a * 68 + nc + 1]       = to_tf32(p1);
            KPs[(row_a + 8) * 68 + nc]     = to_tf32(p2);
            KPs[(row_a + 8) * 68 + nc + 1] = to_tf32(p3);
            Oa[nt][0] *= alA; Oa[nt][1] *= alA;
            Oa[nt][2] *= alB; Oa[nt][3] *= alB;
        }
        psA += __shfl_xor_sync(0xffffffffu, psA, 1);
        psA += __shfl_xor_sync(0xffffffffu, psA, 2);
        psB += __shfl_xor_sync(0xffffffffu, psB, 1);
        psB += __shfl_xor_sync(0xffffffffu, psB, 2);
        if (tig == 0) {
            reds[warpN * 64 + row_a]     = psA;
            reds[warpN * 64 + row_a + 8] = psB;
        }
        if (warpN == 0 && tig == 0) {
            m_s[row_a]     = mA;
            m_s[row_a + 8] = mB;
        }
        __syncthreads();

        if (warpN == 0 && tig == 0) {
            l_s[row_a]     = alA * l_s[row_a]     + reds[row_a]     + reds[64 + row_a];
            l_s[row_a + 8] = alB * l_s[row_a + 8] + reds[row_a + 8] + reds[64 + row_a + 8];
        }

        #pragma unroll
        for (int kk = 0; kk < 64; kk += 8) {
            uint32_t a0 = KPu[(row_a)     * 68 + kk + tig];
            uint32_t a1 = KPu[(row_a + 8) * 68 + kk + tig];
            uint32_t a2 = KPu[(row_a)     * 68 + kk + tig + 4];
            uint32_t a3 = KPu[(row_a + 8) * 68 + kk + tig + 4];
            #pragma unroll
            for (int nt = 0; nt < 4; nt++) {
                int nc = warpN * 32 + nt * 8 + grp;
                uint32_t b0 = Vu[(kk + tig)     * 72 + nc];
                uint32_t b1 = Vu[(kk + tig + 4) * 72 + nc];
                mma_tf32(Oa[nt], a0, a1, a2, a3, b0, b1);
            }
        }
        __syncthreads();
    }

    float rm = rmask[z];
    float invA = rm / l_s[row_a];
    float invB = rm / l_s[row_a + 8];
    #pragma unroll
    for (int nt = 0; nt < 4; nt++) {
        int col = h * 64 + warpN * 32 + nt * 8 + tig * 2;
        long long oA = ((long long)b * Ss + q0 + row_a) * Dd + col;
        long long oB = oA + 8LL * Dd;
        *(__half2*)&ctxh[oA] = __floats2half2_rn(Oa[nt][0] * invA, Oa[nt][1] * invA);
        *(__half2*)&ctxh[oB] = __floats2half2_rn(Oa[nt][2] * invB, Oa[nt][3] * invB);
    }
}

// ---------------- pad row 0 (half ctx) ----------------
__global__ void pad_row_kernel(const float* __restrict__ v, const float* __restrict__ rmask,
                               __half* __restrict__ ctxh)
{
    int z = blockIdx.x;                 // B*H
    int b = z >> 3, h = z & 7;
    int tid = threadIdx.x;              // 256
    int d = tid & 63, chunk = tid >> 6;
    const float* Vg = v + (long long)b * Ss * Dd + h * 64 + d;
    float s = 0.f;
    for (int j = chunk * 128; j < (chunk + 1) * 128; j++)
        s += Vg[(long long)j * Dd];
    __shared__ float red[256];
    red[tid] = s;
    __syncthreads();
    if (tid < 64) {
        float t = red[tid] + red[tid + 64] + red[tid + 128] + red[tid + 192];
        ctxh[(long long)b * Ss * Dd + h * 64 + tid] =
            __float2half_rn(t * (1.0f / Ss) * rmask[z]);
    }
}

// ---------------- residual + LayerNorm (writes fp32 + half mirror) ----------------
__global__ void add_ln_kernel(const float* __restrict__ resid, const float* __restrict__ delta,
                              const float* __restrict__ g, const float* __restrict__ b,
                              float* __restrict__ out, __half* __restrict__ outh)
{
    long long base = (long long)blockIdx.x * Dd;
    int tid = threadIdx.x;
    float v0 = resid[base + tid]       + delta[base + tid];
    float v1 = resid[base + tid + 256] + delta[base + tid + 256];
    float s  = v0 + v1;
    float sq = v0 * v0 + v1 * v1;

    __shared__ float rs[8], rq[8];
    #pragma unroll
    for (int o = 16; o; o >>= 1) {
        s  += __shfl_xor_sync(0xffffffffu, s,  o);
        sq += __shfl_xor_sync(0xffffffffu, sq, o);
    }
    if ((tid & 31) == 0) { rs[tid >> 5] = s; rq[tid >> 5] = sq; }
    __syncthreads();
    s = 0.f; sq = 0.f;
    #pragma unroll
    for (int w2 = 0; w2 < 8; w2++) { s += rs[w2]; sq += rq[w2]; }

    float mu   = s * (1.0f / Dd);
    float var  = sq * (1.0f / Dd) - mu * mu;
    float rstd = rsqrtf(var + 1e-5f);
    float o0 = g[tid]       * ((v0 - mu) * rstd) + b[tid];
    float o1 = g[tid + 256] * ((v1 - mu) * rstd) + b[tid + 256];
    out[base + tid]        = o0;
    out[base + tid + 256]  = o1;
    outh[base + tid]       = __float2half_rn(o0);
    outh[base + tid + 256] = __float2half_rn(o1);
}

// ---------------- head-routing gate: one warp per token ----------------
__global__ void gating_kernel(const float* __restrict__ qlin, const float* __restrict__ wg,
                              float* __restrict__ dyn)
{
    int gw   = (int)((blockIdx.x * blockDim.x + threadIdx.x) >> 5);
    int lane = threadIdx.x & 31;
    if (gw >= Bn * Ss) return;
    const float* q = qlin + (long long)gw * Dd;

    float acc[NGATE];
    #pragma unroll
    for (int g2 = 0; g2 < NGATE; g2++) acc[g2] = 0.f;
    for (int d = lane; d < Dd; d += 32) {
        float qv = q[d];
        const float* w = wg + d * NGATE;
        #pragma unroll
        for (int g2 = 0; g2 < NGATE; g2++) acc[g2] += qv * w[g2];
    }
    #pragma unroll
    for (int g2 = 0; g2 < NGATE; g2++)
        #pragma unroll
        for (int o = 16; o; o >>= 1) acc[g2] += __shfl_xor_sync(0xffffffffu, acc[g2], o);

    if (lane == 0) {
        int i1 = 0;
        #pragma unroll
        for (int g2 = 1; g2 < NGATE; g2++) if (acc[g2] > acc[i1]) i1 = g2;
        int i2 = (i1 == 0) ? 1 : 0;
        #pragma unroll
        for (int g2 = 0; g2 < NGATE; g2++)
            if (g2 != i1 && acc[g2] > acc[i2]) i2 = g2;

        float mx = acc[i1], sum = 0.f, e[NGATE];
        #pragma unroll
        for (int g2 = 0; g2 < NGATE; g2++) { e[g2] = expf(acc[g2] - mx); sum += e[g2]; }
        float inv = 1.0f / sum;
        #pragma unroll
        for (int g2 = 0; g2 < NGATE; g2++)
            dyn[(long long)gw * NGATE + g2] = (g2 == i1 || g2 == i2) ? e[g2] * inv : 0.f;
    }
}

// ---------------- rmask[b,h] ----------------
__global__ void rmask_kernel(const float* __restrict__ dyn, float* __restrict__ rmask)
{
    int z = blockIdx.x;             // B*H
    int b = z / Hh, h = z % Hh;
    int tid = threadIdx.x;          // 256
    if (h < HSs) { if (tid == 0) rmask[z] = 1.f; return; }
    int g = h - HSs;
    float v = dyn[((long long)(b * Ss + tid))       * NGATE + g]
            + dyn[((long long)(b * Ss + tid + 256)) * NGATE + g];
    __shared__ float rs[8];
    #pragma unroll
    for (int o = 16; o; o >>= 1) v += __shfl_xor_sync(0xffffffffu, v, o);
    if ((tid & 31) == 0) rs[tid >> 5] = v;
    __syncthreads();
    if (tid == 0) {
        float t = 0.f;
        #pragma unroll
        for (int w2 = 0; w2 < 8; w2++) t += rs[w2];
        rmask[z] = t * (1.0f / Ss);
    }
}

// ---------------- host orchestration ----------------
struct Wts {
    const float *wq, *bq, *wv, *bv, *wo, *bo, *wg;
    const float *ln1g, *ln1b, *fw1, *fb1, *fw2, *fb2, *ln2g, *ln2b;
};
struct HScr {
    float *qlin, *v, *tmp, *dyn, *rmask;
    __half *xh, *yh, *ctxh, *ffnh;
    __half *wqh, *wvh, *woh, *fw1h, *fw2h;
};

static void gemm_f32out(const __half* A, const __half* Bt, const float* bias, float* C,
                        int M, int N, int K, int relu)
{
    dim3 grid(N / HBN, M / HBM);
    gemm_h_kernel<0><<<grid, 256, H_SMEM>>>(A, Bt, bias, C, nullptr, K, N, relu);
}
static void gemm_h16out(const __half* A, const __half* Bt, const float* bias, __half* C,
                        int M, int N, int K, int relu)
{
    dim3 grid(N / HBN, M / HBM);
    gemm_h_kernel<1><<<grid, 256, H_SMEM>>>(A, Bt, bias, nullptr, C, K, N, relu);
}

static void run_block(float* xq, __half* xqh, __half* xvh, int layer,
                      bool mask_flag, bool apply_pos,
                      const Wts& w, const HScr& s, float* finalOut)
{
    const int M = Bn * Ss;
    const long long DD = (long long)Dd * Dd;

    gemm_f32out(xqh, s.wqh + layer * DD, w.bq + layer * Dd, s.qlin, M, Dd, Dd, 0);
    gemm_f32out(xvh, s.wvh + layer * DD, w.bv + layer * Dd, s.v,    M, Dd, Dd, 0);

    gating_kernel<<<(Bn * Ss * 32 + 255) / 256, 256>>>(
        s.qlin, w.wg + (long long)layer * Dd * NGATE, s.dyn);
    rmask_kernel<<<Bn * Hh, 256>>>(s.dyn, s.rmask);

    flash_attn_kernel<<<dim3(Ss / 64, Bn * Hh), 256, FL_BYTES>>>(
        s.qlin, s.v, s.rmask, s.ctxh, mask_flag ? 1 : 0);
    pad_row_kernel<<<Bn * Hh, 256>>>(s.v, s.rmask, s.ctxh);

    gemm_f32out(s.ctxh, s.woh + layer * DD, w.bo + layer * Dd, s.tmp, M, Dd, Dd, 0);

    add_ln_kernel<<<M, 256>>>(xq, s.tmp, w.ln1g + layer * Dd, w.ln1b + layer * Dd, xq, xqh);

    if (apply_pos) {
        gemm_h16out(xqh, s.fw1h + (long long)layer * Dd * DFFf, w.fb1 + layer * DFFf,
                    s.ffnh, M, DFFf, Dd, 1);
        gemm_f32out(s.ffnh, s.fw2h + (long long)layer * Dd * DFFf, w.fb2 + layer * Dd,
                    s.tmp, M, Dd, DFFf, 0);
        float* out2 = finalOut ? finalOut : xq;
        add_ln_kernel<<<M, 256>>>(xq, s.tmp, w.ln2g + layer * Dd, w.ln2b + layer * Dd,
                                  out2, xqh);
    }
}

extern "C" void kernel_launch(void* const* d_in, const int* in_sizes, int n_in,
                              void* d_out, int out_size)
{
    const float* question    = (const float*)d_in[0];
    const float* interaction = (const float*)d_in[1];
    Wts w;
    w.wq   = (const float*)d_in[2];  w.bq   = (const float*)d_in[3];
    w.wv   = (const float*)d_in[4];  w.bv   = (const float*)d_in[5];
    w.wo   = (const float*)d_in[6];  w.bo   = (const float*)d_in[7];
    w.wg   = (const float*)d_in[8];
    w.ln1g = (const float*)d_in[9];  w.ln1b = (const float*)d_in[10];
    w.fw1  = (const float*)d_in[11]; w.fb1  = (const float*)d_in[12];
    w.fw2  = (const float*)d_in[13]; w.fb2  = (const float*)d_in[14];
    w.ln2g = (const float*)d_in[15]; w.ln2b = (const float*)d_in[16];

    cudaFuncSetAttribute(flash_attn_kernel,
                         cudaFuncAttributeMaxDynamicSharedMemorySize, FL_BYTES);
    cudaFuncSetAttribute(gemm_h_kernel<0>,
                         cudaFuncAttributeMaxDynamicSharedMemorySize, H_SMEM);
    cudaFuncSetAttribute(gemm_h_kernel<1>,
                         cudaFuncAttributeMaxDynamicSharedMemorySize, H_SMEM);

    float *gx, *gy;
    HScr s;
    cudaGetSymbolAddress((void**)&gx,      g_x);
    cudaGetSymbolAddress((void**)&gy,      g_y);
    cudaGetSymbolAddress((void**)&s.qlin,  g_qlin);
    cudaGetSymbolAddress((void**)&s.v,     g_v);
    cudaGetSymbolAddress((void**)&s.tmp,   g_tmp);
    cudaGetSymbolAddress((void**)&s.dyn,   g_dyn);
    cudaGetSymbolAddress((void**)&s.rmask, g_rmask);
    cudaGetSymbolAddress((void**)&s.xh,    g_xh);
    cudaGetSymbolAddress((void**)&s.yh,    g_yh);
    cudaGetSymbolAddress((void**)&s.ctxh,  g_ctxh);
    cudaGetSymbolAddress((void**)&s.ffnh,  g_ffnh);
    cudaGetSymbolAddress((void**)&s.wqh,   g_wqh);
    cudaGetSymbolAddress((void**)&s.wvh,   g_wvh);
    cudaGetSymbolAddress((void**)&s.woh,   g_woh);
    cudaGetSymbolAddress((void**)&s.fw1h,  g_fw1h);
    cudaGetSymbolAddress((void**)&s.fw2h,  g_fw2h);

    size_t bytes = (size_t)Bn * Ss * Dd * sizeof(float);
    cudaMemcpyAsync(gy, interaction, bytes, cudaMemcpyDeviceToDevice);
    cudaMemcpyAsync(gx, question,    bytes, cudaMemcpyDeviceToDevice);

    // embeddings -> half mirrors
    {
        int n = Bn * Ss * Dd;
        f2h_kernel<<<(n + 255) / 256, 256>>>(question, s.xh, interaction, s.yh, n);
    }

    // weights: convert + transpose (wq/wv/wo all layers; fw only layers 3 & 5)
    {
        dim3 blk(32, 8);
        const long long DD = (long long)Dd * Dd;
        transp_h_kernel<<<dim3(16, 16, 6), blk>>>(w.wq, s.wqh, Dd, Dd, DD, DD);
        transp_h_kernel<<<dim3(16, 16, 6), blk>>>(w.wv, s.wvh, Dd, Dd, DD, DD);
        transp_h_kernel<<<dim3(16, 16, 6), blk>>>(w.wo, s.woh, Dd, Dd, DD, DD);
        const long long DF = (long long)Dd * DFFf;
        for (int l = 3; l <= 5; l += 2) {
            transp_h_kernel<<<dim3(DFFf / 32, Dd / 32, 1), blk>>>(
                w.fw1 + l * DF, s.fw1h + l * DF, Dd, DFFf, 0, 0);
            transp_h_kernel<<<dim3(Dd / 32, DFFf / 32, 1), blk>>>(
                w.fw2 + l * DF, s.fw2h + l * DF, DFFf, Dd, 0, 0);
        }
    }

    // knowledge encoder
    run_block(gy, s.yh, s.yh, 0, true,  false, w, s, nullptr);
    run_block(gy, s.yh, s.yh, 1, true,  false, w, s, nullptr);
    // question encoder
    run_block(gx, s.xh, s.xh, 2, true,  false, w, s, nullptr);
    run_block(gx, s.xh, s.yh, 3, false, true,  w, s, nullptr);
    run_block(gx, s.xh, s.xh, 4, true,  false, w, s, nullptr);
    run_block(gx, s.xh, s.yh, 5, false, true,  w, s, (float*)d_out);
}

// round 9
// speedup vs baseline: 3.4414x; 1.0537x over previous
#include <cuda_runtime.h>
#include <cuda_fp16.h>
#include <math.h>
#include <stdint.h>

#define Bn   16
#define Ss   512
#define Dd   512
#define Hh   8
#define HSs  2
#define DKk  64
#define DFFf 2048
#define NGATE 6   // H - HS

// ---------------- scratch (device globals; no allocation allowed) ----------------
__device__ float g_y[Bn*Ss*Dd];
__device__ float g_x[Bn*Ss*Dd];
__device__ float g_tmp[Bn*Ss*Dd];
__device__ float g_dyn[Bn*Ss*NGATE];
__device__ float g_rmask[Bn*Hh];
// half activations
__device__ __half g_xh[Bn*Ss*Dd];
__device__ __half g_yh[Bn*Ss*Dd];
__device__ __half g_qlinh[Bn*Ss*Dd];
__device__ __half g_vh[Bn*Ss*Dd];
__device__ __half g_ctxh[Bn*Ss*Dd];
__device__ __half g_ffnh[Bn*Ss*DFFf];
// transposed half weights
__device__ __half g_wqh[6*Dd*Dd];
__device__ __half g_wvh[6*Dd*Dd];
__device__ __half g_woh[6*Dd*Dd];
__device__ __half g_fw1h[6*Dd*DFFf];   // per layer: [DFF][D]
__device__ __half g_fw2h[6*DFFf*Dd];   // per layer: [D][DFF]

// ---------------- helpers ----------------
__device__ __forceinline__ void mma_f16(float c[4], uint32_t a0, uint32_t a1,
                                        uint32_t a2, uint32_t a3,
                                        uint32_t b0, uint32_t b1) {
    asm volatile(
        "mma.sync.aligned.m16n8k16.row.col.f32.f16.f16.f32 "
        "{%0,%1,%2,%3}, {%4,%5,%6,%7}, {%8,%9}, {%0,%1,%2,%3};"
        : "+f"(c[0]), "+f"(c[1]), "+f"(c[2]), "+f"(c[3])
        : "r"(a0), "r"(a1), "r"(a2), "r"(a3), "r"(b0), "r"(b1));
}

__device__ __forceinline__ uint32_t smem_u32(const void* p) {
    uint32_t a;
    asm("{ .reg .u64 t; cvta.to.shared.u64 t, %1; cvt.u32.u64 %0, t; }"
        : "=r"(a) : "l"(p));
    return a;
}

__device__ __forceinline__ void cp_async16(uint32_t dst, const void* src) {
    asm volatile("cp.async.cg.shared.global [%0], [%1], 16;" :: "r"(dst), "l"(src));
}
__device__ __forceinline__ void cp_commit() {
    asm volatile("cp.async.commit_group;" ::: "memory");
}
template<int NN>
__device__ __forceinline__ void cp_wait() {
    asm volatile("cp.async.wait_group %0;" :: "n"(NN) : "memory");
}

// ---------------- weight convert + transpose: fp32 [R][C] -> half [C][R] ----------------
__global__ void transp_h_kernel(const float* __restrict__ in, __half* __restrict__ out,
                                int R, int C, long long inStride, long long outStride)
{
    __shared__ float t[32][33];
    const float* ip = in + blockIdx.z * inStride;
    __half* op = out + blockIdx.z * outStride;
    int c0 = blockIdx.x * 32, r0 = blockIdx.y * 32;
    int x = threadIdx.x, y0 = threadIdx.y;   // (32,8)
    #pragma unroll
    for (int i = 0; i < 32; i += 8)
        t[y0 + i][x] = ip[(long long)(r0 + y0 + i) * C + c0 + x];
    __syncthreads();
    #pragma unroll
    for (int i = 0; i < 32; i += 8)
        op[(long long)(c0 + y0 + i) * R + r0 + x] = __float2half_rn(t[x][y0 + i]);
}

// ---------------- embeddings fp32 -> half ----------------
__global__ void f2h_kernel(const float* __restrict__ a, __half* __restrict__ ah,
                           const float* __restrict__ b, __half* __restrict__ bh, int n)
{
    int i = blockIdx.x * blockDim.x + threadIdx.x;
    if (i < n) {
        ah[i] = __float2half_rn(a[i]);
        bh[i] = __float2half_rn(b[i]);
    }
}

// ---------------- cp.async 3-stage FP16 GEMM ----------------
#define HBM 128
#define HBN 128
#define HBK 64
#define HLDA 72                    // halves per padded row
#define HSA (HBM * HLDA)           // halves = 9216
#define HSTAGE (2 * HSA)
#define H_SMEM (3 * HSTAGE * 2)    // 110592 bytes

template<int OM>
__global__ void __launch_bounds__(256) gemm_h_kernel(
    const __half* __restrict__ A, const __half* __restrict__ Bt,
    const float* __restrict__ bias, float* __restrict__ Cf, __half* __restrict__ Ch,
    int K, int N, int relu)
{
    extern __shared__ __align__(16) __half smh[];

    const int tid = threadIdx.x;
    const int warpId = tid >> 5;
    const int lane = tid & 31;
    const int grp = lane >> 2;
    const int tig = lane & 3;
    const int warpM = warpId & 1;
    const int warpN = warpId >> 1;
    const int row0 = blockIdx.y * HBM;
    const int col0 = blockIdx.x * HBN;

    const uint32_t sbase = smem_u32(smh);

    auto issue = [&](int kt) {
        const int st = kt % 3;
        const int k0 = kt * HBK;
        const uint32_t sA = sbase + (uint32_t)(st * HSTAGE) * 2u;
        const uint32_t sB = sA + (uint32_t)HSA * 2u;
        #pragma unroll
        for (int i = 0; i < 4; i++) {
            int f4 = tid + i * 256;
            int r = f4 >> 3, c8 = (f4 & 7) * 8;
            cp_async16(sA + (uint32_t)(r * HLDA + c8) * 2u,
                       &A[(long long)(row0 + r) * K + k0 + c8]);
        }
        #pragma unroll
        for (int i = 0; i < 4; i++) {
            int f4 = tid + i * 256;
            int n = f4 >> 3, c8 = (f4 & 7) * 8;
            cp_async16(sB + (uint32_t)(n * HLDA + c8) * 2u,
                       &Bt[(long long)(col0 + n) * K + k0 + c8]);
        }
        cp_commit();
    };

    float acc[4][4][4];
    #pragma unroll
    for (int mt = 0; mt < 4; mt++)
        #pragma unroll
        for (int nt = 0; nt < 4; nt++)
            #pragma unroll
            for (int q = 0; q < 4; q++) acc[mt][nt][q] = 0.f;

    const int KT = K / HBK;
    issue(0);
    if (KT > 1) issue(1);

    for (int kt = 0; kt < KT; kt++) {
        if (kt + 1 < KT) cp_wait<1>(); else cp_wait<0>();
        __syncthreads();
        if (kt + 2 < KT) issue(kt + 2);

        const uint32_t* Asu = reinterpret_cast<const uint32_t*>(smh + (kt % 3) * HSTAGE);
        const uint32_t* Bsu = Asu + HSA / 2;

        #pragma unroll
        for (int kk = 0; kk < 4; kk++) {
            const int kw = kk * 8;
            uint32_t af[4][4];
            #pragma unroll
            for (int mt = 0; mt < 4; mt++) {
                int base = (warpM * 64 + mt * 16 + grp) * 36 + kw + tig;
                af[mt][0] = Asu[base];
                af[mt][1] = Asu[base + 8 * 36];
                af[mt][2] = Asu[base + 4];
                af[mt][3] = Asu[base + 8 * 36 + 4];
            }
            uint32_t bf[4][2];
            #pragma unroll
            for (int nt = 0; nt < 4; nt++) {
                int base = (warpN * 32 + nt * 8 + grp) * 36 + kw + tig;
                bf[nt][0] = Bsu[base];
                bf[nt][1] = Bsu[base + 4];
            }
            #pragma unroll
            for (int mt = 0; mt < 4; mt++)
                #pragma unroll
                for (int nt = 0; nt < 4; nt++)
                    mma_f16(acc[mt][nt], af[mt][0], af[mt][1], af[mt][2], af[mt][3],
                            bf[nt][0], bf[nt][1]);
        }
    }

    #pragma unroll
    for (int mt = 0; mt < 4; mt++) {
        #pragma unroll
        for (int nt = 0; nt < 4; nt++) {
            int r0 = row0 + warpM * 64 + mt * 16 + grp;
            int cc = col0 + warpN * 32 + nt * 8 + tig * 2;
            float b0 = bias[cc], b1 = bias[cc + 1];
            float v0 = acc[mt][nt][0] + b0;
            float v1 = acc[mt][nt][1] + b1;
            float v2 = acc[mt][nt][2] + b0;
            float v3 = acc[mt][nt][3] + b1;
            if (relu) {
                v0 = fmaxf(v0, 0.f); v1 = fmaxf(v1, 0.f);
                v2 = fmaxf(v2, 0.f); v3 = fmaxf(v3, 0.f);
            }
            if (OM == 0) {
                *(float2*)&Cf[(long long)r0 * N + cc]       = make_float2(v0, v1);
                *(float2*)&Cf[(long long)(r0 + 8) * N + cc] = make_float2(v2, v3);
            } else {
                *(__half2*)&Ch[(long long)r0 * N + cc]       = __floats2half2_rn(v0, v1);
                *(__half2*)&Ch[(long long)(r0 + 8) * N + cc] = __floats2half2_rn(v2, v3);
            }
        }
    }
}

// ---------------- fused flash attention, FP16 mma ----------------
// smem (halves): Qs[64*72] | KPs[64*72] (K tile, then P) | Vs[64*66] (V^T: [d][j])
// then floats: redm[128] reds[128] m_s[64] l_s[64]
#define F2_QS   0
#define F2_KP   (64*72)
#define F2_VS   (F2_KP + 64*72)
#define F2_FL   (F2_VS + 64*66)           // half offset of float region (even)
#define F2_BYTES (F2_FL*2 + 384*4)        // 26880 + 1536 = 28416

__global__ void __launch_bounds__(256) flash_attn_kernel(
    const __half* __restrict__ qlinh, const __half* __restrict__ vh,
    const float* __restrict__ rmask, __half* __restrict__ ctxh, int mask_flag)
{
    extern __shared__ __align__(16) __half smh[];
    float* fl   = reinterpret_cast<float*>(smh + F2_FL);
    float* redm = fl;
    float* reds = fl + 128;
    float* m_s  = fl + 256;
    float* l_s  = fl + 320;

    const int z = blockIdx.y;           // b*H + h
    const int b = z >> 3, h = z & 7;
    const int q0 = blockIdx.x * 64;
    const __half* Qg = qlinh + (long long)b * Ss * Dd + h * 64;
    const __half* Vg = vh    + (long long)b * Ss * Dd + h * 64;

    const int tid = threadIdx.x;
    const int warpId = tid >> 5, lane = tid & 31;
    const int grp = lane >> 2, tig = lane & 3;
    const int warpM = warpId >> 1, warpN = warpId & 1;
    const int row_a = warpM * 16 + grp;

    // Q tile, pre-scaled by 1/8 (exact in half)
    {
        const __half2 sc = __floats2half2_rn(0.125f, 0.125f);
        #pragma unroll
        for (int i = 0; i < 2; i++) {
            int id = tid + i * 256;
            int r = id >> 3, c8 = (id & 7) * 8;
            uint4 q = *(const uint4*)&Qg[(long long)(q0 + r) * Dd + c8];
            __half2* qh = reinterpret_cast<__half2*>(&q);
            qh[0] = __hmul2(qh[0], sc); qh[1] = __hmul2(qh[1], sc);
            qh[2] = __hmul2(qh[2], sc); qh[3] = __hmul2(qh[3], sc);
            *(uint4*)&smh[F2_QS + r * 72 + c8] = q;
        }
    }
    if (tid < 64) { m_s[tid] = -1e30f; l_s[tid] = 0.f; }

    float Oa[4][4];
    #pragma unroll
    for (int nt = 0; nt < 4; nt++)
        #pragma unroll
        for (int q = 0; q < 4; q++) Oa[nt][q] = 0.f;

    const uint32_t* Qw  = reinterpret_cast<const uint32_t*>(smh + F2_QS);
    const uint32_t* KPw = reinterpret_cast<const uint32_t*>(smh + F2_KP);
    const uint32_t* Vw  = reinterpret_cast<const uint32_t*>(smh + F2_VS);

    const int nTiles = blockIdx.x + 1;

    for (int kt = 0; kt < nTiles; kt++) {
        const int k0 = kt * 64;
        // K tile: raw half rows
        #pragma unroll
        for (int i = 0; i < 2; i++) {
            int id = tid + i * 256;
            int r = id >> 3, c8 = (id & 7) * 8;
            *(uint4*)&smh[F2_KP + r * 72 + c8] =
                *(const uint4*)&Qg[(long long)(k0 + r) * Dd + c8];
        }
        // V tile transposed: Vs[d][j], stride 66 halves
        #pragma unroll
        for (int i = 0; i < 2; i++) {
            int id = tid + i * 256;
            int j = id >> 3, d0 = (id & 7) * 8;
            uint4 vv = *(const uint4*)&Vg[(long long)(k0 + j) * Dd + d0];
            const __half* v8 = reinterpret_cast<const __half*>(&vv);
            #pragma unroll
            for (int t = 0; t < 8; t++)
                smh[F2_VS + (d0 + t) * 66 + j] = v8[t];
        }
        __syncthreads();

        // S = Q @ K^T
        float scf[4][4];
        #pragma unroll
        for (int nt = 0; nt < 4; nt++)
            #pragma unroll
            for (int q = 0; q < 4; q++) scf[nt][q] = 0.f;

        #pragma unroll
        for (int kk = 0; kk < 4; kk++) {
            const int kw = kk * 8;
            uint32_t a0 = Qw[(row_a)     * 36 + kw + tig];
            uint32_t a1 = Qw[(row_a + 8) * 36 + kw + tig];
            uint32_t a2 = Qw[(row_a)     * 36 + kw + tig + 4];
            uint32_t a3 = Qw[(row_a + 8) * 36 + kw + tig + 4];
            #pragma unroll
            for (int nt = 0; nt < 4; nt++) {
                int nc = warpN * 32 + nt * 8 + grp;
                uint32_t b0 = KPw[nc * 36 + kw + tig];
                uint32_t b1 = KPw[nc * 36 + kw + tig + 4];
                mma_f16(scf[nt], a0, a1, a2, a3, b0, b1);
            }
        }

        if (kt == nTiles - 1) {
            int iA = q0 + row_a, iB = iA + 8;
            int limA = iA + (mask_flag ? 1 : 0);
            int limB = iB + (mask_flag ? 1 : 0);
            #pragma unroll
            for (int nt = 0; nt < 4; nt++) {
                int j0 = k0 + warpN * 32 + nt * 8 + tig * 2;
                if (j0     >= limA) scf[nt][0] = -1e30f;
                if (j0 + 1 >= limA) scf[nt][1] = -1e30f;
                if (j0     >= limB) scf[nt][2] = -1e30f;
                if (j0 + 1 >= limB) scf[nt][3] = -1e30f;
            }
        }

        float mA_old = m_s[row_a], mB_old = m_s[row_a + 8];

        float tmA = -1e30f, tmB = -1e30f;
        #pragma unroll
        for (int nt = 0; nt < 4; nt++) {
            tmA = fmaxf(tmA, fmaxf(scf[nt][0], scf[nt][1]));
            tmB = fmaxf(tmB, fmaxf(scf[nt][2], scf[nt][3]));
        }
        tmA = fmaxf(tmA, __shfl_xor_sync(0xffffffffu, tmA, 1));
        tmA = fmaxf(tmA, __shfl_xor_sync(0xffffffffu, tmA, 2));
        tmB = fmaxf(tmB, __shfl_xor_sync(0xffffffffu, tmB, 1));
        tmB = fmaxf(tmB, __shfl_xor_sync(0xffffffffu, tmB, 2));
        if (tig == 0) {
            redm[warpN * 64 + row_a]     = tmA;
            redm[warpN * 64 + row_a + 8] = tmB;
        }
        __syncthreads();   // QK reads of KPs done -> safe to overwrite with P

        float mA = fmaxf(mA_old, fmaxf(redm[row_a],     redm[64 + row_a]));
        float mB = fmaxf(mB_old, fmaxf(redm[row_a + 8], redm[64 + row_a + 8]));
        float alA = __expf(mA_old - mA);
        float alB = __expf(mB_old - mB);

        float psA = 0.f, psB = 0.f;
        #pragma unroll
        for (int nt = 0; nt < 4; nt++) {
            float p0 = __expf(scf[nt][0] - mA);
            float p1 = __expf(scf[nt][1] - mA);
            float p2 = __expf(scf[nt][2] - mB);
            float p3 = __expf(scf[nt][3] - mB);
            psA += p0 + p1; psB += p2 + p3;
            int nc = warpN * 32 + nt * 8 + tig * 2;
            *(__half2*)&smh[F2_KP + (row_a)     * 72 + nc] = __floats2half2_rn(p0, p1);
            *(__half2*)&smh[F2_KP + (row_a + 8) * 72 + nc] = __floats2half2_rn(p2, p3);
            Oa[nt][0] *= alA; Oa[nt][1] *= alA;
            Oa[nt][2] *= alB; Oa[nt][3] *= alB;
        }
        psA += __shfl_xor_sync(0xffffffffu, psA, 1);
        psA += __shfl_xor_sync(0xffffffffu, psA, 2);
        psB += __shfl_xor_sync(0xffffffffu, psB, 1);
        psB += __shfl_xor_sync(0xffffffffu, psB, 2);
        if (tig == 0) {
            reds[warpN * 64 + row_a]     = psA;
            reds[warpN * 64 + row_a + 8] = psB;
        }
        if (warpN == 0 && tig == 0) {
            m_s[row_a]     = mA;
            m_s[row_a + 8] = mB;
        }
        __syncthreads();

        if (warpN == 0 && tig == 0) {
            l_s[row_a]     = alA * l_s[row_a]     + reds[row_a]     + reds[64 + row_a];
            l_s[row_a + 8] = alB * l_s[row_a + 8] + reds[row_a + 8] + reds[64 + row_a + 8];
        }

        // O += P @ V : A = P (half, 36-word rows), B = V^T (half, 33-word rows)
        #pragma unroll
        for (int kk = 0; kk < 4; kk++) {
            const int kw = kk * 8;
            uint32_t a0 = KPw[(row_a)     * 36 + kw + tig];
            uint32_t a1 = KPw[(row_a + 8) * 36 + kw + tig];
            uint32_t a2 = KPw[(row_a)     * 36 + kw + tig + 4];
            uint32_t a3 = KPw[(row_a + 8) * 36 + kw + tig + 4];
            #pragma unroll
            for (int nt = 0; nt < 4; nt++) {
                int nc = warpN * 32 + nt * 8 + grp;
                uint32_t b0 = Vw[nc * 33 + kw + tig];
                uint32_t b1 = Vw[nc * 33 + kw + tig + 4];
                mma_f16(Oa[nt], a0, a1, a2, a3, b0, b1);
            }
        }
        __syncthreads();
    }

    float rm = rmask[z];
    float invA = rm / l_s[row_a];
    float invB = rm / l_s[row_a + 8];
    #pragma unroll
    for (int nt = 0; nt < 4; nt++) {
        int col = h * 64 + warpN * 32 + nt * 8 + tig * 2;
        long long oA = ((long long)b * Ss + q0 + row_a) * Dd + col;
        long long oB = oA + 8LL * Dd;
        *(__half2*)&ctxh[oA] = __floats2half2_rn(Oa[nt][0] * invA, Oa[nt][1] * invA);
        *(__half2*)&ctxh[oB] = __floats2half2_rn(Oa[nt][2] * invB, Oa[nt][3] * invB);
    }
}

// ---------------- pad row 0 (half V, half ctx) ----------------
__global__ void pad_row_kernel(const __half* __restrict__ vh, const float* __restrict__ rmask,
                               __half* __restrict__ ctxh)
{
    int z = blockIdx.x;                 // B*H
    int b = z >> 3, h = z & 7;
    int tid = threadIdx.x;              // 256
    int d = tid & 63, chunk = tid >> 6;
    const __half* Vg = vh + (long long)b * Ss * Dd + h * 64 + d;
    float s = 0.f;
    for (int j = chunk * 128; j < (chunk + 1) * 128; j++)
        s += __half2float(Vg[(long long)j * Dd]);
    __shared__ float red[256];
    red[tid] = s;
    __syncthreads();
    if (tid < 64) {
        float t = red[tid] + red[tid + 64] + red[tid + 128] + red[tid + 192];
        ctxh[(long long)b * Ss * Dd + h * 64 + tid] =
            __float2half_rn(t * (1.0f / Ss) * rmask[z]);
    }
}

// ---------------- residual + LayerNorm (fp32 out + half mirror) ----------------
__global__ void add_ln_kernel(const float* __restrict__ resid, const float* __restrict__ delta,
                              const float* __restrict__ g, const float* __restrict__ b,
                              float* __restrict__ out, __half* __restrict__ outh)
{
    long long base = (long long)blockIdx.x * Dd;
    int tid = threadIdx.x;
    float v0 = resid[base + tid]       + delta[base + tid];
    float v1 = resid[base + tid + 256] + delta[base + tid + 256];
    float s  = v0 + v1;
    float sq = v0 * v0 + v1 * v1;

    __shared__ float rs[8], rq[8];
    #pragma unroll
    for (int o = 16; o; o >>= 1) {
        s  += __shfl_xor_sync(0xffffffffu, s,  o);
        sq += __shfl_xor_sync(0xffffffffu, sq, o);
    }
    if ((tid & 31) == 0) { rs[tid >> 5] = s; rq[tid >> 5] = sq; }
    __syncthreads();
    s = 0.f; sq = 0.f;
    #pragma unroll
    for (int w2 = 0; w2 < 8; w2++) { s += rs[w2]; sq += rq[w2]; }

    float mu   = s * (1.0f / Dd);
    float var  = sq * (1.0f / Dd) - mu * mu;
    float rstd = rsqrtf(var + 1e-5f);
    float o0 = g[tid]       * ((v0 - mu) * rstd) + b[tid];
    float o1 = g[tid + 256] * ((v1 - mu) * rstd) + b[tid + 256];
    out[base + tid]        = o0;
    out[base + tid + 256]  = o1;
    outh[base + tid]       = __float2half_rn(o0);
    outh[base + tid + 256] = __float2half_rn(o1);
}

// ---------------- head-routing gate: one warp per token (half qlin) ----------------
__global__ void gating_kernel(const __half* __restrict__ qlinh, const float* __restrict__ wg,
                              float* __restrict__ dyn)
{
    int gw   = (int)((blockIdx.x * blockDim.x + threadIdx.x) >> 5);
    int lane = threadIdx.x & 31;
    if (gw >= Bn * Ss) return;
    const __half* q = qlinh + (long long)gw * Dd;

    float acc[NGATE];
    #pragma unroll
    for (int g2 = 0; g2 < NGATE; g2++) acc[g2] = 0.f;
    for (int d = lane; d < Dd; d += 32) {
        float qv = __half2float(q[d]);
        const float* w = wg + d * NGATE;
        #pragma unroll
        for (int g2 = 0; g2 < NGATE; g2++) acc[g2] += qv * w[g2];
    }
    #pragma unroll
    for (int g2 = 0; g2 < NGATE; g2++)
        #pragma unroll
        for (int o = 16; o; o >>= 1) acc[g2] += __shfl_xor_sync(0xffffffffu, acc[g2], o);

    if (lane == 0) {
        int i1 = 0;
        #pragma unroll
        for (int g2 = 1; g2 < NGATE; g2++) if (acc[g2] > acc[i1]) i1 = g2;
        int i2 = (i1 == 0) ? 1 : 0;
        #pragma unroll
        for (int g2 = 0; g2 < NGATE; g2++)
            if (g2 != i1 && acc[g2] > acc[i2]) i2 = g2;

        float mx = acc[i1], sum = 0.f, e[NGATE];
        #pragma unroll
        for (int g2 = 0; g2 < NGATE; g2++) { e[g2] = expf(acc[g2] - mx); sum += e[g2]; }
        float inv = 1.0f / sum;
        #pragma unroll
        for (int g2 = 0; g2 < NGATE; g2++)
            dyn[(long long)gw * NGATE + g2] = (g2 == i1 || g2 == i2) ? e[g2] * inv : 0.f;
    }
}

// ---------------- rmask[b,h] ----------------
__global__ void rmask_kernel(const float* __restrict__ dyn, float* __restrict__ rmask)
{
    int z = blockIdx.x;             // B*H
    int b = z / Hh, h = z % Hh;
    int tid = threadIdx.x;          // 256
    if (h < HSs) { if (tid == 0) rmask[z] = 1.f; return; }
    int g = h - HSs;
    float v = dyn[((long long)(b * Ss + tid))       * NGATE + g]
            + dyn[((long long)(b * Ss + tid + 256)) * NGATE + g];
    __shared__ float rs[8];
    #pragma unroll
    for (int o = 16; o; o >>= 1) v += __shfl_xor_sync(0xffffffffu, v, o);
    if ((tid & 31) == 0) rs[tid >> 5] = v;
    __syncthreads();
    if (tid == 0) {
        float t = 0.f;
        #pragma unroll
        for (int w2 = 0; w2 < 8; w2++) t += rs[w2];
        rmask[z] = t * (1.0f / Ss);
    }
}

// ---------------- host orchestration ----------------
struct Wts {
    const float *wq, *bq, *wv, *bv, *wo, *bo, *wg;
    const float *ln1g, *ln1b, *fw1, *fb1, *fw2, *fb2, *ln2g, *ln2b;
};
struct HScr {
    float *tmp, *dyn, *rmask;
    __half *xh, *yh, *qlinh, *vhh, *ctxh, *ffnh;
    __half *wqh, *wvh, *woh, *fw1h, *fw2h;
};

static void gemm_f32out(const __half* A, const __half* Bt, const float* bias, float* C,
                        int M, int N, int K, int relu)
{
    dim3 grid(N / HBN, M / HBM);
    gemm_h_kernel<0><<<grid, 256, H_SMEM>>>(A, Bt, bias, C, nullptr, K, N, relu);
}
static void gemm_h16out(const __half* A, const __half* Bt, const float* bias, __half* C,
                        int M, int N, int K, int relu)
{
    dim3 grid(N / HBN, M / HBM);
    gemm_h_kernel<1><<<grid, 256, H_SMEM>>>(A, Bt, bias, nullptr, C, K, N, relu);
}

static void run_block(float* xq, __half* xqh, __half* xvh, int layer,
                      bool mask_flag, bool apply_pos,
                      const Wts& w, const HScr& s, float* finalOut)
{
    const int M = Bn * Ss;
    const long long DD = (long long)Dd * Dd;

    gemm_h16out(xqh, s.wqh + layer * DD, w.bq + layer * Dd, s.qlinh, M, Dd, Dd, 0);
    gemm_h16out(xvh, s.wvh + layer * DD, w.bv + layer * Dd, s.vhh,   M, Dd, Dd, 0);

    gating_kernel<<<(Bn * Ss * 32 + 255) / 256, 256>>>(
        s.qlinh, w.wg + (long long)layer * Dd * NGATE, s.dyn);
    rmask_kernel<<<Bn * Hh, 256>>>(s.dyn, s.rmask);

    flash_attn_kernel<<<dim3(Ss / 64, Bn * Hh), 256, F2_BYTES>>>(
        s.qlinh, s.vhh, s.rmask, s.ctxh, mask_flag ? 1 : 0);
    pad_row_kernel<<<Bn * Hh, 256>>>(s.vhh, s.rmask, s.ctxh);

    gemm_f32out(s.ctxh, s.woh + layer * DD, w.bo + layer * Dd, s.tmp, M, Dd, Dd, 0);

    add_ln_kernel<<<M, 256>>>(xq, s.tmp, w.ln1g + layer * Dd, w.ln1b + layer * Dd, xq, xqh);

    if (apply_pos) {
        gemm_h16out(xqh, s.fw1h + (long long)layer * Dd * DFFf, w.fb1 + layer * DFFf,
                    s.ffnh, M, DFFf, Dd, 1);
        gemm_f32out(s.ffnh, s.fw2h + (long long)layer * Dd * DFFf, w.fb2 + layer * Dd,
                    s.tmp, M, Dd, DFFf, 0);
        float* out2 = finalOut ? finalOut : xq;
        add_ln_kernel<<<M, 256>>>(xq, s.tmp, w.ln2g + layer * Dd, w.ln2b + layer * Dd,
                                  out2, xqh);
    }
}

extern "C" void kernel_launch(void* const* d_in, const int* in_sizes, int n_in,
                              void* d_out, int out_size)
{
    const float* question    = (const float*)d_in[0];
    const float* interaction = (const float*)d_in[1];
    Wts w;
    w.wq   = (const float*)d_in[2];  w.bq   = (const float*)d_in[3];
    w.wv   = (const float*)d_in[4];  w.bv   = (const float*)d_in[5];
    w.wo   = (const float*)d_in[6];  w.bo   = (const float*)d_in[7];
    w.wg   = (const float*)d_in[8];
    w.ln1g = (const float*)d_in[9];  w.ln1b = (const float*)d_in[10];
    w.fw1  = (const float*)d_in[11]; w.fb1  = (const float*)d_in[12];
    w.fw2  = (const float*)d_in[13]; w.fb2  = (const float*)d_in[14];
    w.ln2g = (const float*)d_in[15]; w.ln2b = (const float*)d_in[16];

    cudaFuncSetAttribute(flash_attn_kernel,
                         cudaFuncAttributeMaxDynamicSharedMemorySize, F2_BYTES);
    cudaFuncSetAttribute(gemm_h_kernel<0>,
                         cudaFuncAttributeMaxDynamicSharedMemorySize, H_SMEM);
    cudaFuncSetAttribute(gemm_h_kernel<1>,
                         cudaFuncAttributeMaxDynamicSharedMemorySize, H_SMEM);

    float *gx, *gy;
    HScr s;
    cudaGetSymbolAddress((void**)&gx,      g_x);
    cudaGetSymbolAddress((void**)&gy,      g_y);
    cudaGetSymbolAddress((void**)&s.tmp,   g_tmp);
    cudaGetSymbolAddress((void**)&s.dyn,   g_dyn);
    cudaGetSymbolAddress((void**)&s.rmask, g_rmask);
    cudaGetSymbolAddress((void**)&s.xh,    g_xh);
    cudaGetSymbolAddress((void**)&s.yh,    g_yh);
    cudaGetSymbolAddress((void**)&s.qlinh, g_qlinh);
    cudaGetSymbolAddress((void**)&s.vhh,   g_vh);
    cudaGetSymbolAddress((void**)&s.ctxh,  g_ctxh);
    cudaGetSymbolAddress((void**)&s.ffnh,  g_ffnh);
    cudaGetSymbolAddress((void**)&s.wqh,   g_wqh);
    cudaGetSymbolAddress((void**)&s.wvh,   g_wvh);
    cudaGetSymbolAddress((void**)&s.woh,   g_woh);
    cudaGetSymbolAddress((void**)&s.fw1h,  g_fw1h);
    cudaGetSymbolAddress((void**)&s.fw2h,  g_fw2h);

    size_t bytes = (size_t)Bn * Ss * Dd * sizeof(float);
    cudaMemcpyAsync(gy, interaction, bytes, cudaMemcpyDeviceToDevice);
    cudaMemcpyAsync(gx, question,    bytes, cudaMemcpyDeviceToDevice);

    // embeddings -> half mirrors
    {
        int n = Bn * Ss * Dd;
        f2h_kernel<<<(n + 255) / 256, 256>>>(question, s.xh, interaction, s.yh, n);
    }

    // weights: convert + transpose (wq/wv/wo all layers; fw only layers 3 & 5)
    {
        dim3 blk(32, 8);
        const long long DD = (long long)Dd * Dd;
        transp_h_kernel<<<dim3(16, 16, 6), blk>>>(w.wq, s.wqh, Dd, Dd, DD, DD);
        transp_h_kernel<<<dim3(16, 16, 6), blk>>>(w.wv, s.wvh, Dd, Dd, DD, DD);
        transp_h_kernel<<<dim3(16, 16, 6), blk>>>(w.wo, s.woh, Dd, Dd, DD, DD);
        const long long DF = (long long)Dd * DFFf;
        for (int l = 3; l <= 5; l += 2) {
            transp_h_kernel<<<dim3(DFFf / 32, Dd / 32, 1), blk>>>(
                w.fw1 + l * DF, s.fw1h + l * DF, Dd, DFFf, 0, 0);
            transp_h_kernel<<<dim3(Dd / 32, DFFf / 32, 1), blk>>>(
                w.fw2 + l * DF, s.fw2h + l * DF, DFFf, Dd, 0, 0);
        }
    }

    // knowledge encoder
    run_block(gy, s.yh, s.yh, 0, true,  false, w, s, nullptr);
    run_block(gy, s.yh, s.yh, 1, true,  false, w, s, nullptr);
    // question encoder
    run_block(gx, s.xh, s.xh, 2, true,  false, w, s, nullptr);
    run_block(gx, s.xh, s.yh, 3, false, true,  w, s, nullptr);
    run_block(gx, s.xh, s.xh, 4, true,  false, w, s, nullptr);
    run_block(gx, s.xh, s.yh, 5, false, true,  w, s, (float*)d_out);
}

// round 10
// speedup vs baseline: 3.5705x; 1.0375x over previous
#include <cuda_runtime.h>
#include <cuda_fp16.h>
#include <math.h>
#include <stdint.h>

#define Bn   16
#define Ss   512
#define Dd   512
#define Hh   8
#define HSs  2
#define DKk  64
#define DFFf 2048
#define NGATE 6   // H - HS

// ---------------- scratch (device globals; no allocation allowed) ----------------
__device__ float g_y[Bn*Ss*Dd];
__device__ float g_x[Bn*Ss*Dd];
__device__ float g_tmp[Bn*Ss*Dd];
__device__ float g_dyn[Bn*Ss*NGATE];
__device__ float g_rmask[Bn*Hh];
// half activations
__device__ __half g_xh[Bn*Ss*Dd];
__device__ __half g_yh[Bn*Ss*Dd];
__device__ __half g_qlinh[Bn*Ss*Dd];
__device__ __half g_vh[Bn*Ss*Dd];
__device__ __half g_ctxh[Bn*Ss*Dd];
__device__ __half g_ffnh[Bn*Ss*DFFf];
// transposed half weights
__device__ __half g_wqh[6*Dd*Dd];
__device__ __half g_wvh[6*Dd*Dd];
__device__ __half g_woh[6*Dd*Dd];
__device__ __half g_fw1h[6*Dd*DFFf];   // per layer: [DFF][D]
__device__ __half g_fw2h[6*DFFf*Dd];   // per layer: [D][DFF]

// ---------------- helpers ----------------
__device__ __forceinline__ void mma_f16(float c[4], uint32_t a0, uint32_t a1,
                                        uint32_t a2, uint32_t a3,
                                        uint32_t b0, uint32_t b1) {
    asm volatile(
        "mma.sync.aligned.m16n8k16.row.col.f32.f16.f16.f32 "
        "{%0,%1,%2,%3}, {%4,%5,%6,%7}, {%8,%9}, {%0,%1,%2,%3};"
        : "+f"(c[0]), "+f"(c[1]), "+f"(c[2]), "+f"(c[3])
        : "r"(a0), "r"(a1), "r"(a2), "r"(a3), "r"(b0), "r"(b1));
}

#define LDSM_X4(r0, r1, r2, r3, addr) \
    asm volatile("ldmatrix.sync.aligned.m8n8.x4.shared.b16 {%0,%1,%2,%3}, [%4];" \
                 : "=r"(r0), "=r"(r1), "=r"(r2), "=r"(r3) : "r"(addr))

__device__ __forceinline__ uint32_t smem_u32(const void* p) {
    uint32_t a;
    asm("{ .reg .u64 t; cvta.to.shared.u64 t, %1; cvt.u32.u64 %0, t; }"
        : "=r"(a) : "l"(p));
    return a;
}

__device__ __forceinline__ void cp_async16(uint32_t dst, const void* src) {
    asm volatile("cp.async.cg.shared.global [%0], [%1], 16;" :: "r"(dst), "l"(src));
}
__device__ __forceinline__ void cp_commit() {
    asm volatile("cp.async.commit_group;" ::: "memory");
}
template<int NN>
__device__ __forceinline__ void cp_wait() {
    asm volatile("cp.async.wait_group %0;" :: "n"(NN) : "memory");
}

// ---------------- weight convert + transpose: fp32 [R][C] -> half [C][R] ----------------
__global__ void transp_h_kernel(const float* __restrict__ in, __half* __restrict__ out,
                                int R, int C, long long inStride, long long outStride)
{
    __shared__ float t[32][33];
    const float* ip = in + blockIdx.z * inStride;
    __half* op = out + blockIdx.z * outStride;
    int c0 = blockIdx.x * 32, r0 = blockIdx.y * 32;
    int x = threadIdx.x, y0 = threadIdx.y;   // (32,8)
    #pragma unroll
    for (int i = 0; i < 32; i += 8)
        t[y0 + i][x] = ip[(long long)(r0 + y0 + i) * C + c0 + x];
    __syncthreads();
    #pragma unroll
    for (int i = 0; i < 32; i += 8)
        op[(long long)(c0 + y0 + i) * R + r0 + x] = __float2half_rn(t[x][y0 + i]);
}

// ---------------- embeddings fp32 -> half ----------------
__global__ void f2h_kernel(const float* __restrict__ a, __half* __restrict__ ah,
                           const float* __restrict__ b, __half* __restrict__ bh, int n)
{
    int i = blockIdx.x * blockDim.x + threadIdx.x;
    if (i < n) {
        ah[i] = __float2half_rn(a[i]);
        bh[i] = __float2half_rn(b[i]);
    }
}

// ---------------- cp.async 3-stage FP16 GEMM (ldmatrix fragments) ----------------
#define HBM 128
#define HBN 128
#define HBK 64
#define HLDA 72                    // halves per padded row (36 words -> LDSM conflict-free)
#define HSA (HBM * HLDA)           // halves = 9216
#define HSTAGE (2 * HSA)
#define H_SMEM (3 * HSTAGE * 2)    // 110592 bytes

template<int OM>
__global__ void __launch_bounds__(256) gemm_h_kernel(
    const __half* __restrict__ A, const __half* __restrict__ Bt,
    const float* __restrict__ bias, float* __restrict__ Cf, __half* __restrict__ Ch,
    int K, int N, int relu)
{
    extern __shared__ __align__(16) __half smh[];

    const int tid = threadIdx.x;
    const int warpId = tid >> 5;
    const int lane = tid & 31;
    const int grp = lane >> 2;
    const int tig = lane & 3;
    const int warpM = warpId & 1;
    const int warpN = warpId >> 1;
    const int row0 = blockIdx.y * HBM;
    const int col0 = blockIdx.x * HBN;

    const uint32_t sbase = smem_u32(smh);

    // per-lane ldmatrix base offsets (in halves)
    const uint32_t aOff = (uint32_t)((warpM * 64 + (lane & 15)) * HLDA + ((lane >> 4) << 3));
    const int bg = lane >> 3;                      // 0..3
    const uint32_t bOff = (uint32_t)((warpN * 32 + ((bg >= 2) ? 8 : 0) + (lane & 7)) * HLDA
                                     + ((bg & 1) << 3));

    auto issue = [&](int kt) {
        const int st = kt % 3;
        const int k0 = kt * HBK;
        const uint32_t sA = sbase + (uint32_t)(st * HSTAGE) * 2u;
        const uint32_t sB = sA + (uint32_t)HSA * 2u;
        #pragma unroll
        for (int i = 0; i < 4; i++) {
            int f4 = tid + i * 256;
            int r = f4 >> 3, c8 = (f4 & 7) * 8;
            cp_async16(sA + (uint32_t)(r * HLDA + c8) * 2u,
                       &A[(long long)(row0 + r) * K + k0 + c8]);
        }
        #pragma unroll
        for (int i = 0; i < 4; i++) {
            int f4 = tid + i * 256;
            int n = f4 >> 3, c8 = (f4 & 7) * 8;
            cp_async16(sB + (uint32_t)(n * HLDA + c8) * 2u,
                       &Bt[(long long)(col0 + n) * K + k0 + c8]);
        }
        cp_commit();
    };

    float acc[4][4][4];
    #pragma unroll
    for (int mt = 0; mt < 4; mt++)
        #pragma unroll
        for (int nt = 0; nt < 4; nt++)
            #pragma unroll
            for (int q = 0; q < 4; q++) acc[mt][nt][q] = 0.f;

    const int KT = K / HBK;
    issue(0);
    if (KT > 1) issue(1);

    for (int kt = 0; kt < KT; kt++) {
        if (kt + 1 < KT) cp_wait<1>(); else cp_wait<0>();
        __syncthreads();
        if (kt + 2 < KT) issue(kt + 2);

        const uint32_t sA = sbase + (uint32_t)((kt % 3) * HSTAGE) * 2u;
        const uint32_t sB = sA + (uint32_t)HSA * 2u;

        #pragma unroll
        for (int kk = 0; kk < 4; kk++) {
            const uint32_t kh = (uint32_t)(kk * 16) * 2u;   // byte offset
            uint32_t af[4][4];
            #pragma unroll
            for (int mt = 0; mt < 4; mt++)
                LDSM_X4(af[mt][0], af[mt][1], af[mt][2], af[mt][3],
                        sA + (aOff + (uint32_t)(mt * 16 * HLDA)) * 2u + kh);
            uint32_t bf[4][2];
            LDSM_X4(bf[0][0], bf[0][1], bf[1][0], bf[1][1], sB + bOff * 2u + kh);
            LDSM_X4(bf[2][0], bf[2][1], bf[3][0], bf[3][1],
                    sB + (bOff + (uint32_t)(16 * HLDA)) * 2u + kh);
            #pragma unroll
            for (int mt = 0; mt < 4; mt++)
                #pragma unroll
                for (int nt = 0; nt < 4; nt++)
                    mma_f16(acc[mt][nt], af[mt][0], af[mt][1], af[mt][2], af[mt][3],
                            bf[nt][0], bf[nt][1]);
        }
    }

    #pragma unroll
    for (int mt = 0; mt < 4; mt++) {
        #pragma unroll
        for (int nt = 0; nt < 4; nt++) {
            int r0 = row0 + warpM * 64 + mt * 16 + grp;
            int cc = col0 + warpN * 32 + nt * 8 + tig * 2;
            float b0 = bias[cc], b1 = bias[cc + 1];
            float v0 = acc[mt][nt][0] + b0;
            float v1 = acc[mt][nt][1] + b1;
            float v2 = acc[mt][nt][2] + b0;
            float v3 = acc[mt][nt][3] + b1;
            if (relu) {
                v0 = fmaxf(v0, 0.f); v1 = fmaxf(v1, 0.f);
                v2 = fmaxf(v2, 0.f); v3 = fmaxf(v3, 0.f);
            }
            if (OM == 0) {
                *(float2*)&Cf[(long long)r0 * N + cc]       = make_float2(v0, v1);
                *(float2*)&Cf[(long long)(r0 + 8) * N + cc] = make_float2(v2, v3);
            } else {
                *(__half2*)&Ch[(long long)r0 * N + cc]       = __floats2half2_rn(v0, v1);
                *(__half2*)&Ch[(long long)(r0 + 8) * N + cc] = __floats2half2_rn(v2, v3);
            }
        }
    }
}

// ---------------- fused flash attention, FP16 mma + ldmatrix ----------------
// smem (halves): Qs[64*72] | KPs[64*72] (K tile then P) | Vs[64*72] (V^T [d][j])
// then floats: redm[128] reds[128] m_s[64] l_s[64]
#define F2_QS   0
#define F2_KP   (64*72)
#define F2_VS   (F2_KP + 64*72)
#define F2_FL   (F2_VS + 64*72)
#define F2_BYTES (F2_FL*2 + 384*4)        // 27648 + 1536 = 29184

__global__ void __launch_bounds__(256) flash_attn_kernel(
    const __half* __restrict__ qlinh, const __half* __restrict__ vh,
    const float* __restrict__ rmask, __half* __restrict__ ctxh, int mask_flag)
{
    extern __shared__ __align__(16) __half smh[];
    float* fl   = reinterpret_cast<float*>(smh + F2_FL);
    float* redm = fl;
    float* reds = fl + 128;
    float* m_s  = fl + 256;
    float* l_s  = fl + 320;

    const int z = blockIdx.y;           // b*H + h
    const int b = z >> 3, h = z & 7;
    const int q0 = blockIdx.x * 64;
    const __half* Qg = qlinh + (long long)b * Ss * Dd + h * 64;
    const __half* Vg = vh    + (long long)b * Ss * Dd + h * 64;

    const int tid = threadIdx.x;
    const int warpId = tid >> 5, lane = tid & 31;
    const int grp = lane >> 2, tig = lane & 3;
    const int warpM = warpId >> 1, warpN = warpId & 1;
    const int row_a = warpM * 16 + grp;

    const uint32_t sbase = smem_u32(smh);
    // per-lane ldmatrix base offsets (halves)
    const uint32_t aOff = (uint32_t)((warpM * 16 + (lane & 15)) * 72 + ((lane >> 4) << 3));
    const int bg = lane >> 3;
    const uint32_t bOff = (uint32_t)((warpN * 32 + ((bg >= 2) ? 8 : 0) + (lane & 7)) * 72
                                     + ((bg & 1) << 3));

    // Q tile, pre-scaled by 1/8 (exact in half)
    {
        const __half2 sc = __floats2half2_rn(0.125f, 0.125f);
        #pragma unroll
        for (int i = 0; i < 2; i++) {
            int id = tid + i * 256;
            int r = id >> 3, c8 = (id & 7) * 8;
            uint4 q = *(const uint4*)&Qg[(long long)(q0 + r) * Dd + c8];
            __half2* qh = reinterpret_cast<__half2*>(&q);
            qh[0] = __hmul2(qh[0], sc); qh[1] = __hmul2(qh[1], sc);
            qh[2] = __hmul2(qh[2], sc); qh[3] = __hmul2(qh[3], sc);
            *(uint4*)&smh[F2_QS + r * 72 + c8] = q;
        }
    }
    if (tid < 64) { m_s[tid] = -1e30f; l_s[tid] = 0.f; }

    float Oa[4][4];
    #pragma unroll
    for (int nt = 0; nt < 4; nt++)
        #pragma unroll
        for (int q = 0; q < 4; q++) Oa[nt][q] = 0.f;

    const int nTiles = blockIdx.x + 1;

    for (int kt = 0; kt < nTiles; kt++) {
        const int k0 = kt * 64;
        // K tile: raw half rows
        #pragma unroll
        for (int i = 0; i < 2; i++) {
            int id = tid + i * 256;
            int r = id >> 3, c8 = (id & 7) * 8;
            *(uint4*)&smh[F2_KP + r * 72 + c8] =
                *(const uint4*)&Qg[(long long)(k0 + r) * Dd + c8];
        }
        // V tile transposed: Vs[d][j], stride 72 halves
        #pragma unroll
        for (int i = 0; i < 2; i++) {
            int id = tid + i * 256;
            int j = id >> 3, d0 = (id & 7) * 8;
            uint4 vv = *(const uint4*)&Vg[(long long)(k0 + j) * Dd + d0];
            const __half* v8 = reinterpret_cast<const __half*>(&vv);
            #pragma unroll
            for (int t = 0; t < 8; t++)
                smh[F2_VS + (d0 + t) * 72 + j] = v8[t];
        }
        __syncthreads();

        // S = Q @ K^T
        float scf[4][4];
        #pragma unroll
        for (int nt = 0; nt < 4; nt++)
            #pragma unroll
            for (int q = 0; q < 4; q++) scf[nt][q] = 0.f;

        #pragma unroll
        for (int kk = 0; kk < 4; kk++) {
            const uint32_t kh = (uint32_t)(kk * 16) * 2u;
            uint32_t a0, a1, a2, a3;
            LDSM_X4(a0, a1, a2, a3, sbase + (F2_QS + aOff) * 2u + kh);
            uint32_t bf[4][2];
            LDSM_X4(bf[0][0], bf[0][1], bf[1][0], bf[1][1],
                    sbase + (F2_KP + bOff) * 2u + kh);
            LDSM_X4(bf[2][0], bf[2][1], bf[3][0], bf[3][1],
                    sbase + (F2_KP + bOff + 16 * 72) * 2u + kh);
            #pragma unroll
            for (int nt = 0; nt < 4; nt++)
                mma_f16(scf[nt], a0, a1, a2, a3, bf[nt][0], bf[nt][1]);
        }

        if (kt == nTiles - 1) {
            int iA = q0 + row_a, iB = iA + 8;
            int limA = iA + (mask_flag ? 1 : 0);
            int limB = iB + (mask_flag ? 1 : 0);
            #pragma unroll
            for (int nt = 0; nt < 4; nt++) {
                int j0 = k0 + warpN * 32 + nt * 8 + tig * 2;
                if (j0     >= limA) scf[nt][0] = -1e30f;
                if (j0 + 1 >= limA) scf[nt][1] = -1e30f;
                if (j0     >= limB) scf[nt][2] = -1e30f;
                if (j0 + 1 >= limB) scf[nt][3] = -1e30f;
            }
        }

        float mA_old = m_s[row_a], mB_old = m_s[row_a + 8];

        float tmA = -1e30f, tmB = -1e30f;
        #pragma unroll
        for (int nt = 0; nt < 4; nt++) {
            tmA = fmaxf(tmA, fmaxf(scf[nt][0], scf[nt][1]));
            tmB = fmaxf(tmB, fmaxf(scf[nt][2], scf[nt][3]));
        }
        tmA = fmaxf(tmA, __shfl_xor_sync(0xffffffffu, tmA, 1));
        tmA = fmaxf(tmA, __shfl_xor_sync(0xffffffffu, tmA, 2));
        tmB = fmaxf(tmB, __shfl_xor_sync(0xffffffffu, tmB, 1));
        tmB = fmaxf(tmB, __shfl_xor_sync(0xffffffffu, tmB, 2));
        if (tig == 0) {
            redm[warpN * 64 + row_a]     = tmA;
            redm[warpN * 64 + row_a + 8] = tmB;
        }
        __syncthreads();   // QK reads of KPs done -> safe to overwrite with P

        float mA = fmaxf(mA_old, fmaxf(redm[row_a],     redm[64 + row_a]));
        float mB = fmaxf(mB_old, fmaxf(redm[row_a + 8], redm[64 + row_a + 8]));
        float alA = __expf(mA_old - mA);
        float alB = __expf(mB_old - mB);

        float psA = 0.f, psB = 0.f;
        #pragma unroll
        for (int nt = 0; nt < 4; nt++) {
            float p0 = __expf(scf[nt][0] - mA);
            float p1 = __expf(scf[nt][1] - mA);
            float p2 = __expf(scf[nt][2] - mB);
            float p3 = __expf(scf[nt][3] - mB);
            psA += p0 + p1; psB += p2 + p3;
            int nc = warpN * 32 + nt * 8 + tig * 2;
            *(__half2*)&smh[F2_KP + (row_a)     * 72 + nc] = __floats2half2_rn(p0, p1);
            *(__half2*)&smh[F2_KP + (row_a + 8) * 72 + nc] = __floats2half2_rn(p2, p3);
            Oa[nt][0] *= alA; Oa[nt][1] *= alA;
            Oa[nt][2] *= alB; Oa[nt][3] *= alB;
        }
        psA += __shfl_xor_sync(0xffffffffu, psA, 1);
        psA += __shfl_xor_sync(0xffffffffu, psA, 2);
        psB += __shfl_xor_sync(0xffffffffu, psB, 1);
        psB += __shfl_xor_sync(0xffffffffu, psB, 2);
        if (tig == 0) {
            reds[warpN * 64 + row_a]     = psA;
            reds[warpN * 64 + row_a + 8] = psB;
        }
        if (warpN == 0 && tig == 0) {
            m_s[row_a]     = mA;
            m_s[row_a + 8] = mB;
        }
        __syncthreads();

        if (warpN == 0 && tig == 0) {
            l_s[row_a]     = alA * l_s[row_a]     + reds[row_a]     + reds[64 + row_a];
            l_s[row_a + 8] = alB * l_s[row_a + 8] + reds[row_a + 8] + reds[64 + row_a + 8];
        }

        // O += P @ V : A = P (KPs), B = V^T (Vs), both 72-half stride
        #pragma unroll
        for (int kk = 0; kk < 4; kk++) {
            const uint32_t kh = (uint32_t)(kk * 16) * 2u;
            uint32_t a0, a1, a2, a3;
            LDSM_X4(a0, a1, a2, a3, sbase + (F2_KP + aOff) * 2u + kh);
            uint32_t bf[4][2];
            LDSM_X4(bf[0][0], bf[0][1], bf[1][0], bf[1][1],
                    sbase + (F2_VS + bOff) * 2u + kh);
            LDSM_X4(bf[2][0], bf[2][1], bf[3][0], bf[3][1],
                    sbase + (F2_VS + bOff + 16 * 72) * 2u + kh);
            #pragma unroll
            for (int nt = 0; nt < 4; nt++)
                mma_f16(Oa[nt], a0, a1, a2, a3, bf[nt][0], bf[nt][1]);
        }
        __syncthreads();
    }

    float rm = rmask[z];
    float invA = rm / l_s[row_a];
    float invB = rm / l_s[row_a + 8];
    #pragma unroll
    for (int nt = 0; nt < 4; nt++) {
        int col = h * 64 + warpN * 32 + nt * 8 + tig * 2;
        long long oA = ((long long)b * Ss + q0 + row_a) * Dd + col;
        long long oB = oA + 8LL * Dd;
        *(__half2*)&ctxh[oA] = __floats2half2_rn(Oa[nt][0] * invA, Oa[nt][1] * invA);
        *(__half2*)&ctxh[oB] = __floats2half2_rn(Oa[nt][2] * invB, Oa[nt][3] * invB);
    }
}

// ---------------- pad row 0 (half V, half ctx) ----------------
__global__ void pad_row_kernel(const __half* __restrict__ vh, const float* __restrict__ rmask,
                               __half* __restrict__ ctxh)
{
    int z = blockIdx.x;                 // B*H
    int b = z >> 3, h = z & 7;
    int tid = threadIdx.x;              // 256
    int d = tid & 63, chunk = tid >> 6;
    const __half* Vg = vh + (long long)b * Ss * Dd + h * 64 + d;
    float s = 0.f;
    for (int j = chunk * 128; j < (chunk + 1) * 128; j++)
        s += __half2float(Vg[(long long)j * Dd]);
    __shared__ float red[256];
    red[tid] = s;
    __syncthreads();
    if (tid < 64) {
        float t = red[tid] + red[tid + 64] + red[tid + 128] + red[tid + 192];
        ctxh[(long long)b * Ss * Dd + h * 64 + tid] =
            __float2half_rn(t * (1.0f / Ss) * rmask[z]);
    }
}

// ---------------- residual + LayerNorm (fp32 out + half mirror) ----------------
__global__ void add_ln_kernel(const float* __restrict__ resid, const float* __restrict__ delta,
                              const float* __restrict__ g, const float* __restrict__ b,
                              float* __restrict__ out, __half* __restrict__ outh)
{
    long long base = (long long)blockIdx.x * Dd;
    int tid = threadIdx.x;
    float v0 = resid[base + tid]       + delta[base + tid];
    float v1 = resid[base + tid + 256] + delta[base + tid + 256];
    float s  = v0 + v1;
    float sq = v0 * v0 + v1 * v1;

    __shared__ float rs[8], rq[8];
    #pragma unroll
    for (int o = 16; o; o >>= 1) {
        s  += __shfl_xor_sync(0xffffffffu, s,  o);
        sq += __shfl_xor_sync(0xffffffffu, sq, o);
    }
    if ((tid & 31) == 0) { rs[tid >> 5] = s; rq[tid >> 5] = sq; }
    __syncthreads();
    s = 0.f; sq = 0.f;
    #pragma unroll
    for (int w2 = 0; w2 < 8; w2++) { s += rs[w2]; sq += rq[w2]; }

    float mu   = s * (1.0f / Dd);
    float var  = sq * (1.0f / Dd) - mu * mu;
    float rstd = rsqrtf(var + 1e-5f);
    float o0 = g[tid]       * ((v0 - mu) * rstd) + b[tid];
    float o1 = g[tid + 256] * ((v1 - mu) * rstd) + b[tid + 256];
    out[base + tid]        = o0;
    out[base + tid + 256]  = o1;
    outh[base + tid]       = __float2half_rn(o0);
    outh[base + tid + 256] = __float2half_rn(o1);
}

// ---------------- head-routing gate: one warp per token (half qlin) ----------------
__global__ void gating_kernel(const __half* __restrict__ qlinh, const float* __restrict__ wg,
                              float* __restrict__ dyn)
{
    int gw   = (int)((blockIdx.x * blockDim.x + threadIdx.x) >> 5);
    int lane = threadIdx.x & 31;
    if (gw >= Bn * Ss) return;
    const __half* q = qlinh + (long long)gw * Dd;

    float acc[NGATE];
    #pragma unroll
    for (int g2 = 0; g2 < NGATE; g2++) acc[g2] = 0.f;
    for (int d = lane; d < Dd; d += 32) {
        float qv = __half2float(q[d]);
        const float* w = wg + d * NGATE;
        #pragma unroll
        for (int g2 = 0; g2 < NGATE; g2++) acc[g2] += qv * w[g2];
    }
    #pragma unroll
    for (int g2 = 0; g2 < NGATE; g2++)
        #pragma unroll
        for (int o = 16; o; o >>= 1) acc[g2] += __shfl_xor_sync(0xffffffffu, acc[g2], o);

    if (lane == 0) {
        int i1 = 0;
        #pragma unroll
        for (int g2 = 1; g2 < NGATE; g2++) if (acc[g2] > acc[i1]) i1 = g2;
        int i2 = (i1 == 0) ? 1 : 0;
        #pragma unroll
        for (int g2 = 0; g2 < NGATE; g2++)
            if (g2 != i1 && acc[g2] > acc[i2]) i2 = g2;

        float mx = acc[i1], sum = 0.f, e[NGATE];
        #pragma unroll
        for (int g2 = 0; g2 < NGATE; g2++) { e[g2] = expf(acc[g2] - mx); sum += e[g2]; }
        float inv = 1.0f / sum;
        #pragma unroll
        for (int g2 = 0; g2 < NGATE; g2++)
            dyn[(long long)gw * NGATE + g2] = (g2 == i1 || g2 == i2) ? e[g2] * inv : 0.f;
    }
}

// ---------------- rmask[b,h] ----------------
__global__ void rmask_kernel(const float* __restrict__ dyn, float* __restrict__ rmask)
{
    int z = blockIdx.x;             // B*H
    int b = z / Hh, h = z % Hh;
    int tid = threadIdx.x;          // 256
    if (h < HSs) { if (tid == 0) rmask[z] = 1.f; return; }
    int g = h - HSs;
    float v = dyn[((long long)(b * Ss + tid))       * NGATE + g]
            + dyn[((long long)(b * Ss + tid + 256)) * NGATE + g];
    __shared__ float rs[8];
    #pragma unroll
    for (int o = 16; o; o >>= 1) v += __shfl_xor_sync(0xffffffffu, v, o);
    if ((tid & 31) == 0) rs[tid >> 5] = v;
    __syncthreads();
    if (tid == 0) {
        float t = 0.f;
        #pragma unroll
        for (int w2 = 0; w2 < 8; w2++) t += rs[w2];
        rmask[z] = t * (1.0f / Ss);
    }
}

// ---------------- host orchestration ----------------
struct Wts {
    const float *wq, *bq, *wv, *bv, *wo, *bo, *wg;
    const float *ln1g, *ln1b, *fw1, *fb1, *fw2, *fb2, *ln2g, *ln2b;
};
struct HScr {
    float *tmp, *dyn, *rmask;
    __half *xh, *yh, *qlinh, *vhh, *ctxh, *ffnh;
    __half *wqh, *wvh, *woh, *fw1h, *fw2h;
};

static void gemm_f32out(const __half* A, const __half* Bt, const float* bias, float* C,
                        int M, int N, int K, int relu)
{
    dim3 grid(N / HBN, M / HBM);
    gemm_h_kernel<0><<<grid, 256, H_SMEM>>>(A, Bt, bias, C, nullptr, K, N, relu);
}
static void gemm_h16out(const __half* A, const __half* Bt, const float* bias, __half* C,
                        int M, int N, int K, int relu)
{
    dim3 grid(N / HBN, M / HBM);
    gemm_h_kernel<1><<<grid, 256, H_SMEM>>>(A, Bt, bias, nullptr, C, K, N, relu);
}

static void run_block(float* xq, __half* xqh, __half* xvh, int layer,
                      bool mask_flag, bool apply_pos,
                      const Wts& w, const HScr& s, float* finalOut)
{
    const int M = Bn * Ss;
    const long long DD = (long long)Dd * Dd;

    gemm_h16out(xqh, s.wqh + layer * DD, w.bq + layer * Dd, s.qlinh, M, Dd, Dd, 0);
    gemm_h16out(xvh, s.wvh + layer * DD, w.bv + layer * Dd, s.vhh,   M, Dd, Dd, 0);

    gating_kernel<<<(Bn * Ss * 32 + 255) / 256, 256>>>(
        s.qlinh, w.wg + (long long)layer * Dd * NGATE, s.dyn);
    rmask_kernel<<<Bn * Hh, 256>>>(s.dyn, s.rmask);

    flash_attn_kernel<<<dim3(Ss / 64, Bn * Hh), 256, F2_BYTES>>>(
        s.qlinh, s.vhh, s.rmask, s.ctxh, mask_flag ? 1 : 0);
    pad_row_kernel<<<Bn * Hh, 256>>>(s.vhh, s.rmask, s.ctxh);

    gemm_f32out(s.ctxh, s.woh + layer * DD, w.bo + layer * Dd, s.tmp, M, Dd, Dd, 0);

    add_ln_kernel<<<M, 256>>>(xq, s.tmp, w.ln1g + layer * Dd, w.ln1b + layer * Dd, xq, xqh);

    if (apply_pos) {
        gemm_h16out(xqh, s.fw1h + (long long)layer * Dd * DFFf, w.fb1 + layer * DFFf,
                    s.ffnh, M, DFFf, Dd, 1);
        gemm_f32out(s.ffnh, s.fw2h + (long long)layer * Dd * DFFf, w.fb2 + layer * Dd,
                    s.tmp, M, Dd, DFFf, 0);
        float* out2 = finalOut ? finalOut : xq;
        add_ln_kernel<<<M, 256>>>(xq, s.tmp, w.ln2g + layer * Dd, w.ln2b + layer * Dd,
                                  out2, xqh);
    }
}

extern "C" void kernel_launch(void* const* d_in, const int* in_sizes, int n_in,
                              void* d_out, int out_size)
{
    const float* question    = (const float*)d_in[0];
    const float* interaction = (const float*)d_in[1];
    Wts w;
    w.wq   = (const float*)d_in[2];  w.bq   = (const float*)d_in[3];
    w.wv   = (const float*)d_in[4];  w.bv   = (const float*)d_in[5];
    w.wo   = (const float*)d_in[6];  w.bo   = (const float*)d_in[7];
    w.wg   = (const float*)d_in[8];
    w.ln1g = (const float*)d_in[9];  w.ln1b = (const float*)d_in[10];
    w.fw1  = (const float*)d_in[11]; w.fb1  = (const float*)d_in[12];
    w.fw2  = (const float*)d_in[13]; w.fb2  = (const float*)d_in[14];
    w.ln2g = (const float*)d_in[15]; w.ln2b = (const float*)d_in[16];

    cudaFuncSetAttribute(flash_attn_kernel,
                         cudaFuncAttributeMaxDynamicSharedMemorySize, F2_BYTES);
    cudaFuncSetAttribute(gemm_h_kernel<0>,
                         cudaFuncAttributeMaxDynamicSharedMemorySize, H_SMEM);
    cudaFuncSetAttribute(gemm_h_kernel<1>,
                         cudaFuncAttributeMaxDynamicSharedMemorySize, H_SMEM);

    float *gx, *gy;
    HScr s;
    cudaGetSymbolAddress((void**)&gx,      g_x);
    cudaGetSymbolAddress((void**)&gy,      g_y);
    cudaGetSymbolAddress((void**)&s.tmp,   g_tmp);
    cudaGetSymbolAddress((void**)&s.dyn,   g_dyn);
    cudaGetSymbolAddress((void**)&s.rmask, g_rmask);
    cudaGetSymbolAddress((void**)&s.xh,    g_xh);
    cudaGetSymbolAddress((void**)&s.yh,    g_yh);
    cudaGetSymbolAddress((void**)&s.qlinh, g_qlinh);
    cudaGetSymbolAddress((void**)&s.vhh,   g_vh);
    cudaGetSymbolAddress((void**)&s.ctxh,  g_ctxh);
    cudaGetSymbolAddress((void**)&s.ffnh,  g_ffnh);
    cudaGetSymbolAddress((void**)&s.wqh,   g_wqh);
    cudaGetSymbolAddress((void**)&s.wvh,   g_wvh);
    cudaGetSymbolAddress((void**)&s.woh,   g_woh);
    cudaGetSymbolAddress((void**)&s.fw1h,  g_fw1h);
    cudaGetSymbolAddress((void**)&s.fw2h,  g_fw2h);

    size_t bytes = (size_t)Bn * Ss * Dd * sizeof(float);
    cudaMemcpyAsync(gy, interaction, bytes, cudaMemcpyDeviceToDevice);
    cudaMemcpyAsync(gx, question,    bytes, cudaMemcpyDeviceToDevice);

    // embeddings -> half mirrors
    {
        int n = Bn * Ss * Dd;
        f2h_kernel<<<(n + 255) / 256, 256>>>(question, s.xh, interaction, s.yh, n);
    }

    // weights: convert + transpose (wq/wv/wo all layers; fw only layers 3 & 5)
    {
        dim3 blk(32, 8);
        const long long DD = (long long)Dd * Dd;
        transp_h_kernel<<<dim3(16, 16, 6), blk>>>(w.wq, s.wqh, Dd, Dd, DD, DD);
        transp_h_kernel<<<dim3(16, 16, 6), blk>>>(w.wv, s.wvh, Dd, Dd, DD, DD);
        transp_h_kernel<<<dim3(16, 16, 6), blk>>>(w.wo, s.woh, Dd, Dd, DD, DD);
        const long long DF = (long long)Dd * DFFf;
        for (int l = 3; l <= 5; l += 2) {
            transp_h_kernel<<<dim3(DFFf / 32, Dd / 32, 1), blk>>>(
                w.fw1 + l * DF, s.fw1h + l * DF, Dd, DFFf, 0, 0);
            transp_h_kernel<<<dim3(Dd / 32, DFFf / 32, 1), blk>>>(
                w.fw2 + l * DF, s.fw2h + l * DF, DFFf, Dd, 0, 0);
        }
    }

    // knowledge encoder
    run_block(gy, s.yh, s.yh, 0, true,  false, w, s, nullptr);
    run_block(gy, s.yh, s.yh, 1, true,  false, w, s, nullptr);
    // question encoder
    run_block(gx, s.xh, s.xh, 2, true,  false, w, s, nullptr);
    run_block(gx, s.xh, s.yh, 3, false, true,  w, s, nullptr);
    run_block(gx, s.xh, s.xh, 4, true,  false, w, s, nullptr);
    run_block(gx, s.xh, s.yh, 5, false, true,  w, s, (float*)d_out);
}

// round 11
// speedup vs baseline: 3.6791x; 1.0304x over previous
#include <cuda_runtime.h>
#include <cuda_fp16.h>
#include <math.h>
#include <stdint.h>

#define Bn   16
#define Ss   512
#define Dd   512
#define Hh   8
#define HSs  2
#define DFFf 2048
#define NGATE 6   // H - HS
#define QVLD 1024 // combined q||v row stride

// ---------------- scratch (device globals; no allocation allowed) ----------------
__device__ float g_y[Bn*Ss*Dd];
__device__ float g_x[Bn*Ss*Dd];
__device__ float g_tmp[Bn*Ss*Dd];
__device__ float g_dyn[Bn*Ss*NGATE];
__device__ float g_rmask[Bn*Hh];
__device__ float g_bqv[6*QVLD];
// half activations
__device__ __half g_xh[Bn*Ss*Dd];
__device__ __half g_yh[Bn*Ss*Dd];
__device__ __half g_qvh[Bn*Ss*QVLD];      // q (cols 0-511) || v (512-1023)
__device__ __half g_ctxh[Bn*Ss*Dd];
__device__ __half g_ffnh[Bn*Ss*DFFf];
// transposed half weights
__device__ __half g_wqvh[6*QVLD*Dd];      // per layer: [1024 n][512 k], q rows then v rows
__device__ __half g_woh[6*Dd*Dd];
__device__ __half g_fw1h[6*Dd*DFFf];      // per layer: [DFF][D]
__device__ __half g_fw2h[6*DFFf*Dd];      // per layer: [D][DFF]

// ---------------- helpers ----------------
__device__ __forceinline__ void mma_f16(float c[4], uint32_t a0, uint32_t a1,
                                        uint32_t a2, uint32_t a3,
                                        uint32_t b0, uint32_t b1) {
    asm volatile(
        "mma.sync.aligned.m16n8k16.row.col.f32.f16.f16.f32 "
        "{%0,%1,%2,%3}, {%4,%5,%6,%7}, {%8,%9}, {%0,%1,%2,%3};"
        : "+f"(c[0]), "+f"(c[1]), "+f"(c[2]), "+f"(c[3])
        : "r"(a0), "r"(a1), "r"(a2), "r"(a3), "r"(b0), "r"(b1));
}

#define LDSM_X4(r0, r1, r2, r3, addr) \
    asm volatile("ldmatrix.sync.aligned.m8n8.x4.shared.b16 {%0,%1,%2,%3}, [%4];" \
                 : "=r"(r0), "=r"(r1), "=r"(r2), "=r"(r3) : "r"(addr))

__device__ __forceinline__ uint32_t smem_u32(const void* p) {
    uint32_t a;
    asm("{ .reg .u64 t; cvta.to.shared.u64 t, %1; cvt.u32.u64 %0, t; }"
        : "=r"(a) : "l"(p));
    return a;
}

__device__ __forceinline__ void cp_async16(uint32_t dst, const void* src) {
    asm volatile("cp.async.cg.shared.global [%0], [%1], 16;" :: "r"(dst), "l"(src));
}
__device__ __forceinline__ void cp_commit() {
    asm volatile("cp.async.commit_group;" ::: "memory");
}
template<int NN>
__device__ __forceinline__ void cp_wait() {
    asm volatile("cp.async.wait_group %0;" :: "n"(NN) : "memory");
}

// ---------------- weight convert + transpose: fp32 [R][C] -> half [C][R] ----------------
__global__ void transp_h_kernel(const float* __restrict__ in, __half* __restrict__ out,
                                int R, int C, long long inStride, long long outStride)
{
    __shared__ float t[32][33];
    const float* ip = in + blockIdx.z * inStride;
    __half* op = out + blockIdx.z * outStride;
    int c0 = blockIdx.x * 32, r0 = blockIdx.y * 32;
    int x = threadIdx.x, y0 = threadIdx.y;   // (32,8)
    #pragma unroll
    for (int i = 0; i < 32; i += 8)
        t[y0 + i][x] = ip[(long long)(r0 + y0 + i) * C + c0 + x];
    __syncthreads();
    #pragma unroll
    for (int i = 0; i < 32; i += 8)
        op[(long long)(c0 + y0 + i) * R + r0 + x] = __float2half_rn(t[x][y0 + i]);
}

// ---------------- embeddings fp32 -> half + bias concat ----------------
__global__ void f2h_kernel(const float* __restrict__ a, __half* __restrict__ ah,
                           const float* __restrict__ b, __half* __restrict__ bh, int n)
{
    int i = blockIdx.x * blockDim.x + threadIdx.x;
    if (i < n) {
        ah[i] = __float2half_rn(a[i]);
        bh[i] = __float2half_rn(b[i]);
    }
}

__global__ void bias_concat_kernel(const float* __restrict__ bq, const float* __restrict__ bv,
                                   float* __restrict__ bqv)
{
    int i = blockIdx.x * blockDim.x + threadIdx.x;   // 6*1024
    if (i < 6 * QVLD) {
        int l = i >> 10, n = i & 1023;
        bqv[i] = (n < Dd) ? bq[l * Dd + n] : bv[l * Dd + n - Dd];
    }
}

// ---------------- cp.async 3-stage FP16 GEMM (ldmatrix fragments) ----------------
#define HBM 128
#define HBN 128
#define HBK 64
#define HLDA 72
#define HSA (HBM * HLDA)           // 9216 halves
#define HSTAGE (2 * HSA)
#define H_SMEM (3 * HSTAGE * 2)    // 110592 bytes

template<int OM>
__global__ void __launch_bounds__(256) gemm_h_kernel(
    const __half* __restrict__ A, const __half* __restrict__ Bt,
    const float* __restrict__ bias, float* __restrict__ Cf, __half* __restrict__ Ch,
    int K, int Ncols, int ldc, int relu)
{
    extern __shared__ __align__(16) __half smh[];

    const int tid = threadIdx.x;
    const int warpId = tid >> 5;
    const int lane = tid & 31;
    const int grp = lane >> 2;
    const int tig = lane & 3;
    const int warpM = warpId & 1;
    const int warpN = warpId >> 1;
    const int row0 = blockIdx.y * HBM;
    const int col0 = blockIdx.x * HBN;

    const uint32_t sbase = smem_u32(smh);

    const uint32_t aOff = (uint32_t)((warpM * 64 + (lane & 15)) * HLDA + ((lane >> 4) << 3));
    const int bg = lane >> 3;
    const uint32_t bOff = (uint32_t)((warpN * 32 + ((bg >= 2) ? 8 : 0) + (lane & 7)) * HLDA
                                     + ((bg & 1) << 3));

    auto issue = [&](int kt) {
        const int st = kt % 3;
        const int k0 = kt * HBK;
        const uint32_t sA = sbase + (uint32_t)(st * HSTAGE) * 2u;
        const uint32_t sB = sA + (uint32_t)HSA * 2u;
        #pragma unroll
        for (int i = 0; i < 4; i++) {
            int f4 = tid + i * 256;
            int r = f4 >> 3, c8 = (f4 & 7) * 8;
            cp_async16(sA + (uint32_t)(r * HLDA + c8) * 2u,
                       &A[(long long)(row0 + r) * K + k0 + c8]);
        }
        #pragma unroll
        for (int i = 0; i < 4; i++) {
            int f4 = tid + i * 256;
            int n = f4 >> 3, c8 = (f4 & 7) * 8;
            cp_async16(sB + (uint32_t)(n * HLDA + c8) * 2u,
                       &Bt[(long long)(col0 + n) * K + k0 + c8]);
        }
        cp_commit();
    };

    float acc[4][4][4];
    #pragma unroll
    for (int mt = 0; mt < 4; mt++)
        #pragma unroll
        for (int nt = 0; nt < 4; nt++)
            #pragma unroll
            for (int q = 0; q < 4; q++) acc[mt][nt][q] = 0.f;

    const int KT = K / HBK;
    issue(0);
    if (KT > 1) issue(1);

    for (int kt = 0; kt < KT; kt++) {
        if (kt + 1 < KT) cp_wait<1>(); else cp_wait<0>();
        __syncthreads();
        if (kt + 2 < KT) issue(kt + 2);

        const uint32_t sA = sbase + (uint32_t)((kt % 3) * HSTAGE) * 2u;
        const uint32_t sB = sA + (uint32_t)HSA * 2u;

        #pragma unroll
        for (int kk = 0; kk < 4; kk++) {
            const uint32_t kh = (uint32_t)(kk * 16) * 2u;
            uint32_t af[4][4];
            #pragma unroll
            for (int mt = 0; mt < 4; mt++)
                LDSM_X4(af[mt][0], af[mt][1], af[mt][2], af[mt][3],
                        sA + (aOff + (uint32_t)(mt * 16 * HLDA)) * 2u + kh);
            uint32_t bf[4][2];
            LDSM_X4(bf[0][0], bf[0][1], bf[1][0], bf[1][1], sB + bOff * 2u + kh);
            LDSM_X4(bf[2][0], bf[2][1], bf[3][0], bf[3][1],
                    sB + (bOff + (uint32_t)(16 * HLDA)) * 2u + kh);
            #pragma unroll
            for (int mt = 0; mt < 4; mt++)
                #pragma unroll
                for (int nt = 0; nt < 4; nt++)
                    mma_f16(acc[mt][nt], af[mt][0], af[mt][1], af[mt][2], af[mt][3],
                            bf[nt][0], bf[nt][1]);
        }
    }

    #pragma unroll
    for (int mt = 0; mt < 4; mt++) {
        #pragma unroll
        for (int nt = 0; nt < 4; nt++) {
            int r0 = row0 + warpM * 64 + mt * 16 + grp;
            int cc = col0 + warpN * 32 + nt * 8 + tig * 2;
            float b0 = bias[cc], b1 = bias[cc + 1];
            float v0 = acc[mt][nt][0] + b0;
            float v1 = acc[mt][nt][1] + b1;
            float v2 = acc[mt][nt][2] + b0;
            float v3 = acc[mt][nt][3] + b1;
            if (relu) {
                v0 = fmaxf(v0, 0.f); v1 = fmaxf(v1, 0.f);
                v2 = fmaxf(v2, 0.f); v3 = fmaxf(v3, 0.f);
            }
            if (OM == 0) {
                *(float2*)&Cf[(long long)r0 * ldc + cc]       = make_float2(v0, v1);
                *(float2*)&Cf[(long long)(r0 + 8) * ldc + cc] = make_float2(v2, v3);
            } else {
                *(__half2*)&Ch[(long long)r0 * ldc + cc]       = __floats2half2_rn(v0, v1);
                *(__half2*)&Ch[(long long)(r0 + 8) * ldc + cc] = __floats2half2_rn(v2, v3);
            }
        }
    }
}

// ---------------- fused flash attention (FP16 mma + ldmatrix + pad-row fusion) ----------------
// Q/K/V read from combined qv buffer, row stride QVLD (V = cols 512+).
// Last q-tile block also accumulates column means of V and writes ctx row 0.
#define F2_QS   0
#define F2_KP   (64*72)
#define F2_VS   (F2_KP + 64*72)
#define F2_FL   (F2_VS + 64*72)
#define F2_BYTES (F2_FL*2 + 384*4)        // 29184

__global__ void __launch_bounds__(256) flash_attn_kernel(
    const __half* __restrict__ qv,
    const float* __restrict__ rmask, __half* __restrict__ ctxh, int mask_flag)
{
    extern __shared__ __align__(16) __half smh[];
    float* fl   = reinterpret_cast<float*>(smh + F2_FL);
    float* redm = fl;
    float* reds = fl + 128;
    float* m_s  = fl + 256;
    float* l_s  = fl + 320;

    const int z = blockIdx.y;           // b*H + h
    const int b = z >> 3, h = z & 7;
    const int q0 = blockIdx.x * 64;
    const __half* Qg = qv + (long long)b * Ss * QVLD + h * 64;
    const __half* Vg = Qg + Dd;         // v half of combined buffer

    const int tid = threadIdx.x;
    const int warpId = tid >> 5, lane = tid & 31;
    const int grp = lane >> 2, tig = lane & 3;
    const int warpM = warpId >> 1, warpN = warpId & 1;
    const int row_a = warpM * 16 + grp;
    const bool doPad = (blockIdx.x == (Ss / 64 - 1));

    const uint32_t sbase = smem_u32(smh);
    const uint32_t aOff = (uint32_t)((warpM * 16 + (lane & 15)) * 72 + ((lane >> 4) << 3));
    const int bg = lane >> 3;
    const uint32_t bOff = (uint32_t)((warpN * 32 + ((bg >= 2) ? 8 : 0) + (lane & 7)) * 72
                                     + ((bg & 1) << 3));

    // Q tile, pre-scaled by 1/8
    {
        const __half2 sc = __floats2half2_rn(0.125f, 0.125f);
        #pragma unroll
        for (int i = 0; i < 2; i++) {
            int id = tid + i * 256;
            int r = id >> 3, c8 = (id & 7) * 8;
            uint4 q = *(const uint4*)&Qg[(long long)(q0 + r) * QVLD + c8];
            __half2* qh = reinterpret_cast<__half2*>(&q);
            qh[0] = __hmul2(qh[0], sc); qh[1] = __hmul2(qh[1], sc);
            qh[2] = __hmul2(qh[2], sc); qh[3] = __hmul2(qh[3], sc);
            *(uint4*)&smh[F2_QS + r * 72 + c8] = q;
        }
    }
    if (tid < 64) { m_s[tid] = -1e30f; l_s[tid] = 0.f; }

    float Oa[4][4];
    #pragma unroll
    for (int nt = 0; nt < 4; nt++)
        #pragma unroll
        for (int q = 0; q < 4; q++) Oa[nt][q] = 0.f;

    float vsum = 0.f;                    // pad-row accumulator (block 7 only)
    const int padD = tid & 63, padJ0 = (tid >> 6) * 16;

    const int nTiles = blockIdx.x + 1;

    for (int kt = 0; kt < nTiles; kt++) {
        const int k0 = kt * 64;
        #pragma unroll
        for (int i = 0; i < 2; i++) {
            int id = tid + i * 256;
            int r = id >> 3, c8 = (id & 7) * 8;
            *(uint4*)&smh[F2_KP + r * 72 + c8] =
                *(const uint4*)&Qg[(long long)(k0 + r) * QVLD + c8];
        }
        #pragma unroll
        for (int i = 0; i < 2; i++) {
            int id = tid + i * 256;
            int j = id >> 3, d0 = (id & 7) * 8;
            uint4 vv = *(const uint4*)&Vg[(long long)(k0 + j) * QVLD + d0];
            const __half* v8 = reinterpret_cast<const __half*>(&vv);
            #pragma unroll
            for (int t = 0; t < 8; t++)
                smh[F2_VS + (d0 + t) * 72 + j] = v8[t];
        }
        __syncthreads();

        if (doPad) {                      // accumulate V column sums from smem
            #pragma unroll
            for (int jj = 0; jj < 16; jj++)
                vsum += __half2float(smh[F2_VS + padD * 72 + padJ0 + jj]);
        }

        float scf[4][4];
        #pragma unroll
        for (int nt = 0; nt < 4; nt++)
            #pragma unroll
            for (int q = 0; q < 4; q++) scf[nt][q] = 0.f;

        #pragma unroll
        for (int kk = 0; kk < 4; kk++) {
            const uint32_t kh = (uint32_t)(kk * 16) * 2u;
            uint32_t a0, a1, a2, a3;
            LDSM_X4(a0, a1, a2, a3, sbase + (F2_QS + aOff) * 2u + kh);
            uint32_t bf[4][2];
            LDSM_X4(bf[0][0], bf[0][1], bf[1][0], bf[1][1],
                    sbase + (F2_KP + bOff) * 2u + kh);
            LDSM_X4(bf[2][0], bf[2][1], bf[3][0], bf[3][1],
                    sbase + (F2_KP + bOff + 16 * 72) * 2u + kh);
            #pragma unroll
            for (int nt = 0; nt < 4; nt++)
                mma_f16(scf[nt], a0, a1, a2, a3, bf[nt][0], bf[nt][1]);
        }

        if (kt == nTiles - 1) {
            int iA = q0 + row_a, iB = iA + 8;
            int limA = iA + (mask_flag ? 1 : 0);
            int limB = iB + (mask_flag ? 1 : 0);
            #pragma unroll
            for (int nt = 0; nt < 4; nt++) {
                int j0 = k0 + warpN * 32 + nt * 8 + tig * 2;
                if (j0     >= limA) scf[nt][0] = -1e30f;
                if (j0 + 1 >= limA) scf[nt][1] = -1e30f;
                if (j0     >= limB) scf[nt][2] = -1e30f;
                if (j0 + 1 >= limB) scf[nt][3] = -1e30f;
            }
        }

        float mA_old = m_s[row_a], mB_old = m_s[row_a + 8];

        float tmA = -1e30f, tmB = -1e30f;
        #pragma unroll
        for (int nt = 0; nt < 4; nt++) {
            tmA = fmaxf(tmA, fmaxf(scf[nt][0], scf[nt][1]));
            tmB = fmaxf(tmB, fmaxf(scf[nt][2], scf[nt][3]));
        }
        tmA = fmaxf(tmA, __shfl_xor_sync(0xffffffffu, tmA, 1));
        tmA = fmaxf(tmA, __shfl_xor_sync(0xffffffffu, tmA, 2));
        tmB = fmaxf(tmB, __shfl_xor_sync(0xffffffffu, tmB, 1));
        tmB = fmaxf(tmB, __shfl_xor_sync(0xffffffffu, tmB, 2));
        if (tig == 0) {
            redm[warpN * 64 + row_a]     = tmA;
            redm[warpN * 64 + row_a + 8] = tmB;
        }
        __syncthreads();

        float mA = fmaxf(mA_old, fmaxf(redm[row_a],     redm[64 + row_a]));
        float mB = fmaxf(mB_old, fmaxf(redm[row_a + 8], redm[64 + row_a + 8]));
        float alA = __expf(mA_old - mA);
        float alB = __expf(mB_old - mB);

        float psA = 0.f, psB = 0.f;
        #pragma unroll
        for (int nt = 0; nt < 4; nt++) {
            float p0 = __expf(scf[nt][0] - mA);
            float p1 = __expf(scf[nt][1] - mA);
            float p2 = __expf(scf[nt][2] - mB);
            float p3 = __expf(scf[nt][3] - mB);
            psA += p0 + p1; psB += p2 + p3;
            int nc = warpN * 32 + nt * 8 + tig * 2;
            *(__half2*)&smh[F2_KP + (row_a)     * 72 + nc] = __floats2half2_rn(p0, p1);
            *(__half2*)&smh[F2_KP + (row_a + 8) * 72 + nc] = __floats2half2_rn(p2, p3);
            Oa[nt][0] *= alA; Oa[nt][1] *= alA;
            Oa[nt][2] *= alB; Oa[nt][3] *= alB;
        }
        psA += __shfl_xor_sync(0xffffffffu, psA, 1);
        psA += __shfl_xor_sync(0xffffffffu, psA, 2);
        psB += __shfl_xor_sync(0xffffffffu, psB, 1);
        psB += __shfl_xor_sync(0xffffffffu, psB, 2);
        if (tig == 0) {
            reds[warpN * 64 + row_a]     = psA;
            reds[warpN * 64 + row_a + 8] = psB;
        }
        if (warpN == 0 && tig == 0) {
            m_s[row_a]     = mA;
            m_s[row_a + 8] = mB;
        }
        __syncthreads();

        if (warpN == 0 && tig == 0) {
            l_s[row_a]     = alA * l_s[row_a]     + reds[row_a]     + reds[64 + row_a];
            l_s[row_a + 8] = alB * l_s[row_a + 8] + reds[row_a + 8] + reds[64 + row_a + 8];
        }

        #pragma unroll
        for (int kk = 0; kk < 4; kk++) {
            const uint32_t kh = (uint32_t)(kk * 16) * 2u;
            uint32_t a0, a1, a2, a3;
            LDSM_X4(a0, a1, a2, a3, sbase + (F2_KP + aOff) * 2u + kh);
            uint32_t bf[4][2];
            LDSM_X4(bf[0][0], bf[0][1], bf[1][0], bf[1][1],
                    sbase + (F2_VS + bOff) * 2u + kh);
            LDSM_X4(bf[2][0], bf[2][1], bf[3][0], bf[3][1],
                    sbase + (F2_VS + bOff + 16 * 72) * 2u + kh);
            #pragma unroll
            for (int nt = 0; nt < 4; nt++)
                mma_f16(Oa[nt], a0, a1, a2, a3, bf[nt][0], bf[nt][1]);
        }
        __syncthreads();
    }

    float rm = rmask[z];

    // pad-row: block 7 writes ctx row 0 = rm * mean_j V
    if (doPad) {
        fl[(tid >> 6) * 64 + padD] = vsum;
        __syncthreads();
        if (tid < 64) {
            float t = fl[tid] + fl[64 + tid] + fl[128 + tid] + fl[192 + tid];
            ctxh[(long long)b * Ss * Dd + h * 64 + tid] =
                __float2half_rn(t * (1.0f / Ss) * rm);
        }
    }

    float invA = rm / l_s[row_a];
    float invB = rm / l_s[row_a + 8];
    const bool skipA = (q0 + row_a == 0);     // row 0 owned by pad path
    #pragma unroll
    for (int nt = 0; nt < 4; nt++) {
        int col = h * 64 + warpN * 32 + nt * 8 + tig * 2;
        long long oA = ((long long)b * Ss + q0 + row_a) * Dd + col;
        long long oB = oA + 8LL * Dd;
        if (!skipA)
            *(__half2*)&ctxh[oA] = __floats2half2_rn(Oa[nt][0] * invA, Oa[nt][1] * invA);
        *(__half2*)&ctxh[oB] = __floats2half2_rn(Oa[nt][2] * invB, Oa[nt][3] * invB);
    }
}

// ---------------- residual + LayerNorm (fp32 out + half mirror) ----------------
__global__ void add_ln_kernel(const float* __restrict__ resid, const float* __restrict__ delta,
                              const float* __restrict__ g, const float* __restrict__ b,
                              float* __restrict__ out, __half* __restrict__ outh)
{
    long long base = (long long)blockIdx.x * Dd;
    int tid = threadIdx.x;
    float v0 = resid[base + tid]       + delta[base + tid];
    float v1 = resid[base + tid + 256] + delta[base + tid + 256];
    float s  = v0 + v1;
    float sq = v0 * v0 + v1 * v1;

    __shared__ float rs[8], rq[8];
    #pragma unroll
    for (int o = 16; o; o >>= 1) {
        s  += __shfl_xor_sync(0xffffffffu, s,  o);
        sq += __shfl_xor_sync(0xffffffffu, sq, o);
    }
    if ((tid & 31) == 0) { rs[tid >> 5] = s; rq[tid >> 5] = sq; }
    __syncthreads();
    s = 0.f; sq = 0.f;
    #pragma unroll
    for (int w2 = 0; w2 < 8; w2++) { s += rs[w2]; sq += rq[w2]; }

    float mu   = s * (1.0f / Dd);
    float var  = sq * (1.0f / Dd) - mu * mu;
    float rstd = rsqrtf(var + 1e-5f);
    float o0 = g[tid]       * ((v0 - mu) * rstd) + b[tid];
    float o1 = g[tid + 256] * ((v1 - mu) * rstd) + b[tid + 256];
    out[base + tid]        = o0;
    out[base + tid + 256]  = o1;
    outh[base + tid]       = __float2half_rn(o0);
    outh[base + tid + 256] = __float2half_rn(o1);
}

// ---------------- head-routing gate: one warp per token (strided qv buffer) ----------------
__global__ void gating_kernel(const __half* __restrict__ qv, const float* __restrict__ wg,
                              float* __restrict__ dyn)
{
    int gw   = (int)((blockIdx.x * blockDim.x + threadIdx.x) >> 5);
    int lane = threadIdx.x & 31;
    if (gw >= Bn * Ss) return;
    const __half* q = qv + (long long)gw * QVLD;

    float acc[NGATE];
    #pragma unroll
    for (int g2 = 0; g2 < NGATE; g2++) acc[g2] = 0.f;
    for (int d = lane; d < Dd; d += 32) {
        float qv2 = __half2float(q[d]);
        const float* w = wg + d * NGATE;
        #pragma unroll
        for (int g2 = 0; g2 < NGATE; g2++) acc[g2] += qv2 * w[g2];
    }
    #pragma unroll
    for (int g2 = 0; g2 < NGATE; g2++)
        #pragma unroll
        for (int o = 16; o; o >>= 1) acc[g2] += __shfl_xor_sync(0xffffffffu, acc[g2], o);

    if (lane == 0) {
        int i1 = 0;
        #pragma unroll
        for (int g2 = 1; g2 < NGATE; g2++) if (acc[g2] > acc[i1]) i1 = g2;
        int i2 = (i1 == 0) ? 1 : 0;
        #pragma unroll
        for (int g2 = 0; g2 < NGATE; g2++)
            if (g2 != i1 && acc[g2] > acc[i2]) i2 = g2;

        float mx = acc[i1], sum = 0.f, e[NGATE];
        #pragma unroll
        for (int g2 = 0; g2 < NGATE; g2++) { e[g2] = expf(acc[g2] - mx); sum += e[g2]; }
        float inv = 1.0f / sum;
        #pragma unroll
        for (int g2 = 0; g2 < NGATE; g2++)
            dyn[(long long)gw * NGATE + g2] = (g2 == i1 || g2 == i2) ? e[g2] * inv : 0.f;
    }
}

// ---------------- rmask[b,h] ----------------
__global__ void rmask_kernel(const float* __restrict__ dyn, float* __restrict__ rmask)
{
    int z = blockIdx.x;             // B*H
    int b = z / Hh, h = z % Hh;
    int tid = threadIdx.x;          // 256
    if (h < HSs) { if (tid == 0) rmask[z] = 1.f; return; }
    int g = h - HSs;
    float v = dyn[((long long)(b * Ss + tid))       * NGATE + g]
            + dyn[((long long)(b * Ss + tid + 256)) * NGATE + g];
    __shared__ float rs[8];
    #pragma unroll
    for (int o = 16; o; o >>= 1) v += __shfl_xor_sync(0xffffffffu, v, o);
    if ((tid & 31) == 0) rs[tid >> 5] = v;
    __syncthreads();
    if (tid == 0) {
        float t = 0.f;
        #pragma unroll
        for (int w2 = 0; w2 < 8; w2++) t += rs[w2];
        rmask[z] = t * (1.0f / Ss);
    }
}

// ---------------- host orchestration ----------------
struct Wts {
    const float *wq, *bq, *wv, *bv, *wo, *bo, *wg;
    const float *ln1g, *ln1b, *fw1, *fb1, *fw2, *fb2, *ln2g, *ln2b;
};
struct HScr {
    float *tmp, *dyn, *rmask, *bqv;
    __half *xh, *yh, *qvh, *ctxh, *ffnh;
    __half *wqvh, *woh, *fw1h, *fw2h;
};

static void gemm_f32out(const __half* A, const __half* Bt, const float* bias, float* C,
                        int M, int Ncols, int ldc, int K, int relu)
{
    dim3 grid(Ncols / HBN, M / HBM);
    gemm_h_kernel<0><<<grid, 256, H_SMEM>>>(A, Bt, bias, C, nullptr, K, Ncols, ldc, relu);
}
static void gemm_h16out(const __half* A, const __half* Bt, const float* bias, __half* C,
                        int M, int Ncols, int ldc, int K, int relu)
{
    dim3 grid(Ncols / HBN, M / HBM);
    gemm_h_kernel<1><<<grid, 256, H_SMEM>>>(A, Bt, bias, nullptr, C, K, Ncols, ldc, relu);
}

static void run_block(float* xq, __half* xqh, __half* xvh, int layer,
                      bool mask_flag, bool apply_pos,
                      const Wts& w, const HScr& s, float* finalOut)
{
    const int M = Bn * Ss;
    const long long DD = (long long)Dd * Dd;
    const __half* wqv = s.wqvh + (long long)layer * QVLD * Dd;

    if (xqh == xvh) {
        // fused q||v projection, one GEMM N=1024
        gemm_h16out(xqh, wqv, s.bqv + layer * QVLD, s.qvh, M, QVLD, QVLD, Dd, 0);
    } else {
        gemm_h16out(xqh, wqv,                 w.bq + layer * Dd, s.qvh,      M, Dd, QVLD, Dd, 0);
        gemm_h16out(xvh, wqv + (long long)Dd * Dd, w.bv + layer * Dd, s.qvh + Dd, M, Dd, QVLD, Dd, 0);
    }

    gating_kernel<<<(Bn * Ss * 32 + 255) / 256, 256>>>(
        s.qvh, w.wg + (long long)layer * Dd * NGATE, s.dyn);
    rmask_kernel<<<Bn * Hh, 256>>>(s.dyn, s.rmask);

    flash_attn_kernel<<<dim3(Ss / 64, Bn * Hh), 256, F2_BYTES>>>(
        s.qvh, s.rmask, s.ctxh, mask_flag ? 1 : 0);

    gemm_f32out(s.ctxh, s.woh + layer * DD, w.bo + layer * Dd, s.tmp, M, Dd, Dd, Dd, 0);

    add_ln_kernel<<<M, 256>>>(xq, s.tmp, w.ln1g + layer * Dd, w.ln1b + layer * Dd, xq, xqh);

    if (apply_pos) {
        gemm_h16out(xqh, s.fw1h + (long long)layer * Dd * DFFf, w.fb1 + layer * DFFf,
                    s.ffnh, M, DFFf, DFFf, Dd, 1);
        gemm_f32out(s.ffnh, s.fw2h + (long long)layer * Dd * DFFf, w.fb2 + layer * Dd,
                    s.tmp, M, Dd, Dd, DFFf, 0);
        float* out2 = finalOut ? finalOut : xq;
        add_ln_kernel<<<M, 256>>>(xq, s.tmp, w.ln2g + layer * Dd, w.ln2b + layer * Dd,
                                  out2, xqh);
    }
}

extern "C" void kernel_launch(void* const* d_in, const int* in_sizes, int n_in,
                              void* d_out, int out_size)
{
    const float* question    = (const float*)d_in[0];
    const float* interaction = (const float*)d_in[1];
    Wts w;
    w.wq   = (const float*)d_in[2];  w.bq   = (const float*)d_in[3];
    w.wv   = (const float*)d_in[4];  w.bv   = (const float*)d_in[5];
    w.wo   = (const float*)d_in[6];  w.bo   = (const float*)d_in[7];
    w.wg   = (const float*)d_in[8];
    w.ln1g = (const float*)d_in[9];  w.ln1b = (const float*)d_in[10];
    w.fw1  = (const float*)d_in[11]; w.fb1  = (const float*)d_in[12];
    w.fw2  = (const float*)d_in[13]; w.fb2  = (const float*)d_in[14];
    w.ln2g = (const float*)d_in[15]; w.ln2b = (const float*)d_in[16];

    cudaFuncSetAttribute(flash_attn_kernel,
                         cudaFuncAttributeMaxDynamicSharedMemorySize, F2_BYTES);
    cudaFuncSetAttribute(gemm_h_kernel<0>,
                         cudaFuncAttributeMaxDynamicSharedMemorySize, H_SMEM);
    cudaFuncSetAttribute(gemm_h_kernel<1>,
                         cudaFuncAttributeMaxDynamicSharedMemorySize, H_SMEM);

    float *gx, *gy;
    HScr s;
    cudaGetSymbolAddress((void**)&gx,      g_x);
    cudaGetSymbolAddress((void**)&gy,      g_y);
    cudaGetSymbolAddress((void**)&s.tmp,   g_tmp);
    cudaGetSymbolAddress((void**)&s.dyn,   g_dyn);
    cudaGetSymbolAddress((void**)&s.rmask, g_rmask);
    cudaGetSymbolAddress((void**)&s.bqv,   g_bqv);
    cudaGetSymbolAddress((void**)&s.xh,    g_xh);
    cudaGetSymbolAddress((void**)&s.yh,    g_yh);
    cudaGetSymbolAddress((void**)&s.qvh,   g_qvh);
    cudaGetSymbolAddress((void**)&s.ctxh,  g_ctxh);
    cudaGetSymbolAddress((void**)&s.ffnh,  g_ffnh);
    cudaGetSymbolAddress((void**)&s.wqvh,  g_wqvh);
    cudaGetSymbolAddress((void**)&s.woh,   g_woh);
    cudaGetSymbolAddress((void**)&s.fw1h,  g_fw1h);
    cudaGetSymbolAddress((void**)&s.fw2h,  g_fw2h);

    size_t bytes = (size_t)Bn * Ss * Dd * sizeof(float);
    cudaMemcpyAsync(gy, interaction, bytes, cudaMemcpyDeviceToDevice);
    cudaMemcpyAsync(gx, question,    bytes, cudaMemcpyDeviceToDevice);

    // embeddings -> half mirrors, bias concat
    {
        int n = Bn * Ss * Dd;
        f2h_kernel<<<(n + 255) / 256, 256>>>(question, s.xh, interaction, s.yh, n);
        bias_concat_kernel<<<(6 * QVLD + 255) / 256, 256>>>(w.bq, w.bv, s.bqv);
    }

    // weights: convert + transpose into combined / separate buffers
    {
        dim3 blk(32, 8);
        const long long DD = (long long)Dd * Dd;
        const long long QV = (long long)QVLD * Dd;
        transp_h_kernel<<<dim3(16, 16, 6), blk>>>(w.wq, s.wqvh, Dd, Dd, DD, QV);
        transp_h_kernel<<<dim3(16, 16, 6), blk>>>(w.wv, s.wqvh + DD, Dd, Dd, DD, QV);
        transp_h_kernel<<<dim3(16, 16, 6), blk>>>(w.wo, s.woh, Dd, Dd, DD, DD);
        const long long DF = (long long)Dd * DFFf;
        for (int l = 3; l <= 5; l += 2) {
            transp_h_kernel<<<dim3(DFFf / 32, Dd / 32, 1), blk>>>(
                w.fw1 + l * DF, s.fw1h + l * DF, Dd, DFFf, 0, 0);
            transp_h_kernel<<<dim3(Dd / 32, DFFf / 32, 1), blk>>>(
                w.fw2 + l * DF, s.fw2h + l * DF, DFFf, Dd, 0, 0);
        }
    }

    // knowledge encoder
    run_block(gy, s.yh, s.yh, 0, true,  false, w, s, nullptr);
    run_block(gy, s.yh, s.yh, 1, true,  false, w, s, nullptr);
    // question encoder
    run_block(gx, s.xh, s.xh, 2, true,  false, w, s, nullptr);
    run_block(gx, s.xh, s.yh, 3, false, true,  w, s, nullptr);
    run_block(gx, s.xh, s.xh, 4, true,  false, w, s, nullptr);
    run_block(gx, s.xh, s.yh, 5, false, true,  w, s, (float*)d_out);
}